// round 13
// baseline (speedup 1.0000x reference)
#include <cuda_runtime.h>
#include <cuda_bf16.h>
#include <math.h>
#include <cstdint>

// ---------------- problem constants ----------------
namespace {
constexpr int NB   = 16;      // batch
constexpr int SEQ  = 2048;    // L
constexpr int DM   = 128;     // d_model
constexpr int DI   = 256;     // d_inner
constexpr int DS   = 16;      // d_state
constexpr int DTR  = 8;       // dt_rank
constexpr int NLAY = 4;
constexpr int NCLS = 5;
constexpr int BL   = NB * SEQ;          // 32768 rows
constexpr int XPD  = DTR + 2 * DS;      // 40
constexpr int NCH  = 32;                // chunks per sequence
constexpr int CH   = SEQ / NCH;         // 64 steps per chunk
constexpr int SCAN_BLOCKS = 256;        // 2 chunks per block; <= co-resident capacity
constexpr float EPS = 1e-5f;
}

typedef unsigned long long ull;

// ---------------- scratch (static __device__, no allocs) ----------------
__device__ float g_h    [BL * DM];            // residual stream
__device__ float g_xz   [BL * 2 * DI];        // in_proj output (xm | z)
__device__ float g_xc   [BL * DI];            // conv+silu output (u), fp32 for scan
__device__ float g_dbc  [BL * XPD];           // x_proj output (dt|B|C)
__device__ float g_P    [NB * NCH * DI * DS];
__device__ float g_S    [NB * NCH * DI * DS];
__device__ float g_H0   [NB * NCH * DI * DS];
__device__ float g_poolp[256 * DM];           // per-mma2-block pool partials

// bf16 hi/lo split activations (A operands)
__device__ __nv_bfloat16 g_xnh[BL * DM],  g_xnl[BL * DM];   // rmsnorm out
__device__ __nv_bfloat16 g_xch[BL * DI],  g_xcl[BL * DI];   // conv out
__device__ __nv_bfloat16 g_yh [BL * DI],  g_yl [BL * DI];   // scan out

// bf16 hi/lo split weights (B operands), xp padded 40->64 rows with zeros
__device__ __nv_bfloat16 g_wih[NLAY * 512 * 128], g_wil[NLAY * 512 * 128];
__device__ __nv_bfloat16 g_wxh[NLAY * 64 * 256],  g_wxl[NLAY * 64 * 256];
__device__ __nv_bfloat16 g_woh[NLAY * 128 * 256], g_wol[NLAY * 128 * 256];

// global software barrier state (generation-based; monotonic across replays)
__device__ unsigned g_cnt = 0;
__device__ volatile unsigned g_gen = 0;

__device__ __forceinline__ void gbar(unsigned nb) {
    __syncthreads();
    if (threadIdx.x == 0) {
        __threadfence();
        unsigned gen = g_gen;
        if (atomicAdd(&g_cnt, 1u) == nb - 1) {
            atomicExch(&g_cnt, 0u);
            __threadfence();
            g_gen = gen + 1;
        } else {
            while (g_gen == gen) { }
        }
        __threadfence();
    }
    __syncthreads();
}

// ---------------- helpers ----------------
__device__ __forceinline__ uint32_t smem_u32(const void* p) {
    uint32_t a;
    asm("{ .reg .u64 t; cvta.to.shared.u64 t, %1; cvt.u32.u64 %0, t; }"
        : "=r"(a) : "l"(p));
    return a;
}
__device__ __forceinline__ void ldsm4(uint32_t a, uint32_t& r0, uint32_t& r1,
                                      uint32_t& r2, uint32_t& r3) {
    asm volatile("ldmatrix.sync.aligned.m8n8.x4.shared.b16 {%0,%1,%2,%3}, [%4];"
                 : "=r"(r0), "=r"(r1), "=r"(r2), "=r"(r3) : "r"(a));
}
__device__ __forceinline__ void hmma(float* c, const uint32_t* a,
                                     uint32_t b0, uint32_t b1) {
    asm volatile(
        "mma.sync.aligned.m16n8k16.row.col.f32.bf16.bf16.f32 "
        "{%0,%1,%2,%3}, {%4,%5,%6,%7}, {%8,%9}, {%0,%1,%2,%3};"
        : "+f"(c[0]), "+f"(c[1]), "+f"(c[2]), "+f"(c[3])
        : "r"(a[0]), "r"(a[1]), "r"(a[2]), "r"(a[3]), "r"(b0), "r"(b1));
}
__device__ __forceinline__ void cpa16(uint32_t dst, const void* src) {
    asm volatile("cp.async.cg.shared.global [%0], [%1], 16;" :: "r"(dst), "l"(src));
}
__device__ __forceinline__ void cpa_commit() {
    asm volatile("cp.async.commit_group;" ::: "memory");
}
template <int N> __device__ __forceinline__ void cpa_wait() {
    asm volatile("cp.async.wait_group %0;" :: "n"(N) : "memory");
}
__device__ __forceinline__ void bf16split(float x, __nv_bfloat16& h, __nv_bfloat16& l) {
    h = __float2bfloat16(x);
    l = __float2bfloat16(x - __bfloat162float(h));
}
// ---- packed f32x2 primitives (lane-exact fp32) ----
__device__ __forceinline__ ull pk2(float lo, float hi) {
    ull r; asm("mov.b64 %0, {%1, %2};" : "=l"(r) : "f"(lo), "f"(hi)); return r;
}
__device__ __forceinline__ void upk2(ull v, float& lo, float& hi) {
    asm("mov.b64 {%0, %1}, %2;" : "=f"(lo), "=f"(hi) : "l"(v));
}
__device__ __forceinline__ ull mul2_(ull a, ull b) {
    ull r; asm("mul.rn.f32x2 %0, %1, %2;" : "=l"(r) : "l"(a), "l"(b)); return r;
}
__device__ __forceinline__ ull fma2_(ull a, ull b, ull c) {
    ull r; asm("fma.rn.f32x2 %0, %1, %2, %3;" : "=l"(r) : "l"(a), "l"(b), "l"(c));
    return r;
}
// packed power ladder: a2[k] = (w^(2k+1), w^(2k+2)), k=0..7
__device__ __forceinline__ void powchain2(float w, ull* a2) {
    float w2 = w * w;
    ull s2 = pk2(w2, w2);
    a2[0] = pk2(w, w2);
#pragma unroll
    for (int k = 1; k < 8; k++) a2[k] = mul2_(a2[k - 1], s2);
}
__device__ __forceinline__ bool a_is_chain(const float* A) {
    bool f = true;
#pragma unroll
    for (int n = 0; n < DS; n++)
        f = f && (fabsf(A[n] - A[0] * (float)(n + 1)) <= 1e-3f * (float)(n + 1));
    return f;
}
__device__ __forceinline__ float softplus_f(float v) {
    return fmaxf(v, 0.0f) + __logf(1.0f + __expf(-fabsf(v)));
}

// ---------------- weight conversion (once per launch) ----------------
__global__ void k_cvtw(const float* __restrict__ in_w,
                       const float* __restrict__ xp_w,
                       const float* __restrict__ out_w) {
    int i = blockIdx.x * 256 + threadIdx.x;
    if (i < NLAY * 512 * 128) {
        __nv_bfloat16 h, l; bf16split(in_w[i], h, l);
        g_wih[i] = h; g_wil[i] = l;
    }
    if (i < NLAY * 64 * 256) {
        int l4 = i / (64 * 256);
        int r  = (i / 256) % 64;
        int c  = i % 256;
        float x = (r < XPD) ? xp_w[((size_t)l4 * XPD + r) * 256 + c] : 0.f;
        __nv_bfloat16 h, l; bf16split(x, h, l);
        g_wxh[i] = h; g_wxl[i] = l;
    }
    if (i < NLAY * 128 * 256) {
        __nv_bfloat16 h, l; bf16split(out_w[i], h, l);
        g_woh[i] = h; g_wol[i] = l;
    }
}

// ---------------- encoder: h = x @ enc_w^T + enc_b, fused layer-0 rmsnorm ----
__global__ void k_encoder(const float* __restrict__ x,
                          const float* __restrict__ ew,
                          const float* __restrict__ eb,
                          const float* __restrict__ nw) {
    int row = blockIdx.x;
    int m   = threadIdx.x;          // 128 threads
    __shared__ float xs[12];
    __shared__ float red[4];
    if (m < 12) xs[m] = x[row * 12 + m];
    __syncthreads();
    float acc = eb[m];
#pragma unroll
    for (int c = 0; c < 12; c++) acc = fmaf(xs[c], ew[m * 12 + c], acc);
    g_h[row * DM + m] = acc;
    float ss = acc * acc;
#pragma unroll
    for (int o = 16; o; o >>= 1) ss += __shfl_xor_sync(0xffffffffu, ss, o);
    if ((m & 31) == 0) red[m >> 5] = ss;
    __syncthreads();
    float tot = red[0] + red[1] + red[2] + red[3];
    float r = rsqrtf(tot * (1.0f / DM) + EPS);
    float o = acc * r * nw[m];
    __nv_bfloat16 h, l; bf16split(o, h, l);
    g_xnh[(size_t)row * DM + m] = h;
    g_xnl[(size_t)row * DM + m] = l;
}

// ---------------- HMMA 3-split GEMM, cp.async pipelined ---------------------
// MODE 0: in_proj  (K=128) -> g_xz  (N=512, grid.y=4)
// MODE 1: x_proj   (K=256) -> g_dbc (N=40 real, TN=64)
// MODE 2: out_proj (K=256) -> g_h   (accumulate) + fused next-rmsnorm (nwp)
//         or fused final rmsnorm+pool partials (poolw) on the last layer.
template <int MODE>
__global__ void __launch_bounds__(256, 2) k_mma(int layer,
                                                const float* __restrict__ nwp,
                                                const float* __restrict__ poolw) {
    constexpr int K   = (MODE == 0) ? 128 : 256;
    constexpr int TN  = (MODE == 1) ? 64 : 128;
    constexpr int NF  = TN / 16;
    constexpr bool ACC = (MODE == 2);
    constexpr int STR = 40;                       // smem row stride (bf16)
    constexpr int NC  = K / 32;                   // k-chunks
    constexpr int ASZ = 128 * STR * 2;            // bytes per A tile
    constexpr int BSZ = TN * STR * 2;             // bytes per B tile
    constexpr int STG = 2 * ASZ + 2 * BSZ;        // bytes per stage
    constexpr int CTSTR = 132;                    // fp32 epilogue tile stride

    extern __shared__ __align__(16) char sm[];

    const __nv_bfloat16* Ah = (MODE == 0) ? g_xnh : (MODE == 1 ? g_xch : g_yh);
    const __nv_bfloat16* Al = (MODE == 0) ? g_xnl : (MODE == 1 ? g_xcl : g_yl);
    const __nv_bfloat16* Wh;
    const __nv_bfloat16* Wl;
    if (MODE == 0) {
        Wh = g_wih + (size_t)layer * 512 * 128;
        Wl = g_wil + (size_t)layer * 512 * 128;
    } else if (MODE == 1) {
        Wh = g_wxh + (size_t)layer * 64 * 256;
        Wl = g_wxl + (size_t)layer * 64 * 256;
    } else {
        Wh = g_woh + (size_t)layer * 128 * 256;
        Wl = g_wol + (size_t)layer * 128 * 256;
    }
    float* C  = (MODE == 0) ? g_xz : (MODE == 1 ? g_dbc : g_h);
    const int ldC = (MODE == 0) ? 512 : (MODE == 1 ? XPD : DM);

    const int tid = threadIdx.x;
    const int lid = tid & 31;
    const int wid = tid >> 5;
    const int mw  = wid & 3;
    const int nw  = wid >> 2;
    const int bm  = blockIdx.x * 128;
    const int bn  = blockIdx.y * TN;
    const int rb0 = mw * 32;
    const int nb0 = nw * (TN / 2);

    const uint32_t sb0 = smem_u32(sm);

    auto stage_fn = [&](int kc, int st) {
        uint32_t base = sb0 + (uint32_t)st * STG;
#pragma unroll
        for (int s = tid; s < 512; s += 256) {
            int row = s >> 2, c8 = (s & 3) * 8;
            size_t go = (size_t)(bm + row) * K + kc * 32 + c8;
            uint32_t so = (uint32_t)(row * STR + c8) * 2;
            cpa16(base + so, Ah + go);
            cpa16(base + ASZ + so, Al + go);
        }
#pragma unroll
        for (int s = tid; s < TN * 4; s += 256) {
            int row = s >> 2, c8 = (s & 3) * 8;
            size_t go = (size_t)(bn + row) * K + kc * 32 + c8;
            uint32_t so = (uint32_t)(row * STR + c8) * 2;
            cpa16(base + 2 * ASZ + so, Wh + go);
            cpa16(base + 2 * ASZ + BSZ + so, Wl + go);
        }
        cpa_commit();
    };

    const int arow = (lid & 7) + ((lid >> 3) & 1) * 8;
    const int acol = (lid >> 4) * 8;
    const int brow = (lid & 7) + ((lid >> 3) >= 2 ? 8 : 0);
    const int bcol = ((lid >> 3) & 1) * 8;

    float acc[2][NF][4];
#pragma unroll
    for (int mi = 0; mi < 2; mi++)
#pragma unroll
        for (int ni = 0; ni < NF; ni++)
#pragma unroll
            for (int q = 0; q < 4; q++) acc[mi][ni][q] = 0.f;

    stage_fn(0, 0);
    if (NC > 1) stage_fn(1, 1);

    for (int kc = 0; kc < NC; kc++) {
        if (kc + 1 < NC) cpa_wait<1>(); else cpa_wait<0>();
        __syncthreads();
        uint32_t base = sb0 + (uint32_t)(kc & 1) * STG;
        uint32_t bAh = base, bAl = base + ASZ;
        uint32_t bBh = base + 2 * ASZ, bBl = base + 2 * ASZ + BSZ;
#pragma unroll
        for (int ks = 0; ks < 32; ks += 16) {
            uint32_t ah[2][4], al[2][4];
#pragma unroll
            for (int mi = 0; mi < 2; mi++) {
                uint32_t aoff =
                    (uint32_t)(((rb0 + mi * 16 + arow) * STR + ks + acol) * 2);
                ldsm4(bAh + aoff, ah[mi][0], ah[mi][1], ah[mi][2], ah[mi][3]);
                ldsm4(bAl + aoff, al[mi][0], al[mi][1], al[mi][2], al[mi][3]);
            }
#pragma unroll
            for (int ng = 0; ng < NF; ng += 4) {
                uint32_t bh[4][2], bl[4][2];
#pragma unroll
                for (int lj = 0; lj < 2; lj++) {
                    int rowb = nb0 + (ng / 2 + lj) * 16;
                    uint32_t boff =
                        (uint32_t)(((rowb + brow) * STR + ks + bcol) * 2);
                    uint32_t r0, r1, r2, r3;
                    ldsm4(bBh + boff, r0, r1, r2, r3);
                    bh[lj * 2][0] = r0; bh[lj * 2][1] = r1;
                    bh[lj * 2 + 1][0] = r2; bh[lj * 2 + 1][1] = r3;
                    ldsm4(bBl + boff, r0, r1, r2, r3);
                    bl[lj * 2][0] = r0; bl[lj * 2][1] = r1;
                    bl[lj * 2 + 1][0] = r2; bl[lj * 2 + 1][1] = r3;
                }
#pragma unroll
                for (int mi = 0; mi < 2; mi++)
#pragma unroll
                    for (int nf = 0; nf < 4; nf++) {
                        float* a = acc[mi][ng + nf];
                        hmma(a, ah[mi], bh[nf][0], bh[nf][1]);
                        hmma(a, al[mi], bh[nf][0], bh[nf][1]);
                        hmma(a, ah[mi], bl[nf][0], bl[nf][1]);
                    }
            }
        }
        __syncthreads();
        if (kc + 2 < NC) stage_fn(kc + 2, kc & 1);
    }

    // epilogue
    float* ct = reinterpret_cast<float*>(sm);   // fp32 tile for MODE 2 fusion
    const int g = lid >> 2, t = lid & 3;
#pragma unroll
    for (int mi = 0; mi < 2; mi++) {
        int row0 = bm + rb0 + mi * 16 + g;
#pragma unroll
        for (int ni = 0; ni < NF; ni++) {
            int col = bn + nb0 + ni * 8 + t * 2;
            if (MODE == 1 && col >= XPD) continue;
            float2* p0 = reinterpret_cast<float2*>(C + (size_t)row0 * ldC + col);
            float2* p1 = reinterpret_cast<float2*>(C + (size_t)(row0 + 8) * ldC + col);
            float2 v0 = make_float2(acc[mi][ni][0], acc[mi][ni][1]);
            float2 v1 = make_float2(acc[mi][ni][2], acc[mi][ni][3]);
            if (ACC) {
                float2 o0 = *p0, o1 = *p1;
                v0.x += o0.x; v0.y += o0.y; v1.x += o1.x; v1.y += o1.y;
            }
            *p0 = v0; *p1 = v1;
            if (MODE == 2) {
                int lr0 = rb0 + mi * 16 + g;
                ct[lr0 * CTSTR + col] = v0.x; ct[lr0 * CTSTR + col + 1] = v0.y;
                ct[(lr0 + 8) * CTSTR + col] = v1.x; ct[(lr0 + 8) * CTSTR + col + 1] = v1.y;
            }
        }
    }
    if (MODE == 2 && nwp != nullptr) {
        __syncthreads();
        float4 wv = reinterpret_cast<const float4*>(nwp)[lid];
#pragma unroll 4
        for (int rr = 0; rr < 16; rr++) {
            int lr = wid * 16 + rr;
            float4 v = *reinterpret_cast<const float4*>(ct + lr * CTSTR + lid * 4);
            float ss = v.x * v.x + v.y * v.y + v.z * v.z + v.w * v.w;
#pragma unroll
            for (int o = 16; o; o >>= 1) ss += __shfl_xor_sync(0xffffffffu, ss, o);
            float rn = rsqrtf(ss * (1.0f / DM) + EPS);
            float o0 = v.x * rn * wv.x, o1 = v.y * rn * wv.y;
            float o2 = v.z * rn * wv.z, o3 = v.w * rn * wv.w;
            __nv_bfloat16 h0, l0, h1, l1, h2, l2, h3, l3;
            bf16split(o0, h0, l0); bf16split(o1, h1, l1);
            bf16split(o2, h2, l2); bf16split(o3, h3, l3);
            size_t base = (size_t)(bm + lr) * DM + lid * 4;
            *reinterpret_cast<__nv_bfloat162*>(g_xnh + base)     = __nv_bfloat162(h0, h1);
            *reinterpret_cast<__nv_bfloat162*>(g_xnh + base + 2) = __nv_bfloat162(h2, h3);
            *reinterpret_cast<__nv_bfloat162*>(g_xnl + base)     = __nv_bfloat162(l0, l1);
            *reinterpret_cast<__nv_bfloat162*>(g_xnl + base + 2) = __nv_bfloat162(l2, l3);
        }
    }
    if (MODE == 2 && poolw != nullptr) {
        __syncthreads();
        float* spool = reinterpret_cast<float*>(sm + 128 * CTSTR * 4);  // [8][128]
        float4 wv = reinterpret_cast<const float4*>(poolw)[lid];
        float pa0 = 0.f, pa1 = 0.f, pa2 = 0.f, pa3 = 0.f;
#pragma unroll 4
        for (int rr = 0; rr < 16; rr++) {
            int lr = wid * 16 + rr;
            float4 v = *reinterpret_cast<const float4*>(ct + lr * CTSTR + lid * 4);
            float ss = v.x * v.x + v.y * v.y + v.z * v.z + v.w * v.w;
#pragma unroll
            for (int o = 16; o; o >>= 1) ss += __shfl_xor_sync(0xffffffffu, ss, o);
            float rn = rsqrtf(ss * (1.0f / DM) + EPS);
            pa0 = fmaf(v.x * rn, wv.x, pa0);
            pa1 = fmaf(v.y * rn, wv.y, pa1);
            pa2 = fmaf(v.z * rn, wv.z, pa2);
            pa3 = fmaf(v.w * rn, wv.w, pa3);
        }
        __syncthreads();
        spool[wid * DM + lid * 4 + 0] = pa0;
        spool[wid * DM + lid * 4 + 1] = pa1;
        spool[wid * DM + lid * 4 + 2] = pa2;
        spool[wid * DM + lid * 4 + 3] = pa3;
        __syncthreads();
        if (tid < DM) {
            float s = 0.f;
#pragma unroll
            for (int w = 0; w < 8; w++) s += spool[w * DM + tid];
            g_poolp[blockIdx.x * DM + tid] = s;
        }
    }
}

// ---------------- causal depthwise conv + silu -> fp32 u and bf16 hi/lo ----------------
__global__ void k_conv(const float* __restrict__ cw, const float* __restrict__ cb) {
    int d   = threadIdx.x;               // 0..255
    int bl0 = blockIdx.x * 4;            // 4 consecutive rows, same sequence
    int l   = bl0 & (SEQ - 1);
    const float* src = g_xz + (size_t)bl0 * (2 * DI) + d;
    float w0 = cw[d * 4 + 0], w1 = cw[d * 4 + 1], w2 = cw[d * 4 + 2], w3 = cw[d * 4 + 3];
    float b  = cb[d];
    float v0, v1, v2;
    if (l == 0) { v0 = v1 = v2 = 0.f; }
    else { v0 = src[-3 * 512]; v1 = src[-2 * 512]; v2 = src[-512]; }
    float v3 = src[0], v4 = src[512], v5 = src[2 * 512], v6 = src[3 * 512];
    float va[7] = {v0, v1, v2, v3, v4, v5, v6};
#pragma unroll
    for (int j = 0; j < 4; j++) {
        float s = b;
        s = fmaf(va[j + 0], w0, s);
        s = fmaf(va[j + 1], w1, s);
        s = fmaf(va[j + 2], w2, s);
        s = fmaf(va[j + 3], w3, s);
        float sig = __fdividef(1.0f, 1.0f + __expf(-s));
        float u = s * sig;
        size_t idx = (size_t)(bl0 + j) * DI + d;
        g_xc[idx] = u;
        __nv_bfloat16 h, lo; bf16split(u, h, lo);
        g_xch[idx] = h; g_xcl[idx] = lo;
    }
}

// ---------------- fused selective scan (packed f32x2 math) ------------------
// Grid = 256 blocks (one per (b, chunk-pair)), 256 threads (= d).
// __launch_bounds__(256, 2) -> >=2 CTAs/SM -> all blocks co-resident (barrier-safe).
__global__ void __launch_bounds__(256, 2) k_scan(
        const float* __restrict__ Alog, const float* __restrict__ Dpl,
        const float* __restrict__ dtw,  const float* __restrict__ dtb) {
    __shared__ float sdbc[2 * CH * XPD];    // 2 chunks x 64 x 40 floats = 20KB
    const int d  = threadIdx.x;
    const int b  = blockIdx.x >> 4;
    const int cc = blockIdx.x & 15;
    const int c0 = cc * 2;
    const int l0 = b * SEQ + c0 * CH;

    for (int s = d; s < 2 * CH * (XPD / 4); s += DI) {
        reinterpret_cast<float4*>(sdbc)[s] =
            *reinterpret_cast<const float4*>(g_dbc + (size_t)l0 * XPD + s * 4);
    }
    __syncthreads();

    float A[DS];
#pragma unroll
    for (int n = 0; n < DS; n++) A[n] = -__expf(Alog[d * DS + n]);
    const bool fast = a_is_chain(A);
    const float A0 = A[0];
    // packed dt weights: wr2[k] = (w_{2k}, w_{2k+1})
    ull wr2[4];
#pragma unroll
    for (int k = 0; k < 4; k++)
        wr2[k] = pk2(dtw[d * DTR + 2 * k], dtw[d * DTR + 2 * k + 1]);
    const float bb = dtb[d];
    const float Dd = Dpl[d];

    // ---- phase A: local chunk scans -> P, S (packed) ----
#pragma unroll
    for (int p = 0; p < 2; p++) {
        const float* up = g_xc + (size_t)(l0 + p * CH) * DI + d;
        ull S2[8];
#pragma unroll
        for (int k = 0; k < 8; k++) S2[k] = 0ull;
        float dsum = 0.f;
        for (int t = 0; t < CH; t++) {
            const ulonglong2* rp =
                reinterpret_cast<const ulonglong2*>(sdbc + (p * CH + t) * XPD);
            ulonglong2 dt01 = rp[0], dt23 = rp[1];
            ull v2 = mul2_(dt01.x, wr2[0]);
            v2 = fma2_(dt01.y, wr2[1], v2);
            v2 = fma2_(dt23.x, wr2[2], v2);
            v2 = fma2_(dt23.y, wr2[3], v2);
            float vlo, vhi; upk2(v2, vlo, vhi);
            float delta = softplus_f(vlo + vhi + bb);
            float du = delta * up[t * DI];
            dsum += delta;
            ulonglong2 b01 = rp[2], b23 = rp[3], b45 = rp[4], b67 = rp[5];
            ull B2[8] = {b01.x, b01.y, b23.x, b23.y, b45.x, b45.y, b67.x, b67.y};
            if (fast) {
                ull a2[8];
                powchain2(__expf(delta * A0), a2);
                ull du2 = pk2(du, du);
#pragma unroll
                for (int k = 0; k < 8; k++)
                    S2[k] = fma2_(a2[k], S2[k], mul2_(du2, B2[k]));
            } else {
#pragma unroll
                for (int k = 0; k < 8; k++) {
                    float slo, shi, blo2, bhi2;
                    upk2(S2[k], slo, shi); upk2(B2[k], blo2, bhi2);
                    slo = fmaf(__expf(delta * A[2 * k]), slo, du * blo2);
                    shi = fmaf(__expf(delta * A[2 * k + 1]), shi, du * bhi2);
                    S2[k] = pk2(slo, shi);
                }
            }
        }
        int o = (((b * NCH + c0 + p) * DI) + d) * DS;
        ull P2[8];
        if (fast) {
            powchain2(__expf(dsum * A0), P2);
        } else {
#pragma unroll
            for (int k = 0; k < 8; k++)
                P2[k] = pk2(__expf(A[2 * k] * dsum), __expf(A[2 * k + 1] * dsum));
        }
        ulonglong2* Pp = reinterpret_cast<ulonglong2*>(g_P + o);
        ulonglong2* Sp = reinterpret_cast<ulonglong2*>(g_S + o);
#pragma unroll
        for (int q = 0; q < 4; q++) {
            Pp[q] = make_ulonglong2(P2[2 * q], P2[2 * q + 1]);
            Sp[q] = make_ulonglong2(S2[2 * q], S2[2 * q + 1]);
        }
    }

    // ---- phase B: chunk-boundary recurrence ----
    gbar(SCAN_BLOCKS);
    {
        int item = blockIdx.x * 256 + d;
        int bb2 = item >> 12;
        int dn  = item & 4095;
        float h = 0.f;
        for (int c = 0; c < NCH; c++) {
            int o = (bb2 * NCH + c) * DI * DS + dn;
            g_H0[o] = h;
            h = fmaf(g_P[o], h, g_S[o]);
        }
    }
    gbar(SCAN_BLOCKS);

    // ---- phase C: corrected replay -> y (packed) ----
#pragma unroll
    for (int p = 0; p < 2; p++) {
        ull h2[8];
        {
            int o = (((b * NCH + c0 + p) * DI) + d) * DS;
            const ulonglong2* Hp = reinterpret_cast<const ulonglong2*>(g_H0 + o);
#pragma unroll
            for (int q = 0; q < 4; q++) {
                ulonglong2 hv = Hp[q];
                h2[2 * q] = hv.x; h2[2 * q + 1] = hv.y;
            }
        }
        const int lp = l0 + p * CH;
        const float* up = g_xc + (size_t)lp * DI + d;
        const float* zp = g_xz + (size_t)lp * (2 * DI) + DI + d;
        for (int t = 0; t < CH; t++) {
            const ulonglong2* rp =
                reinterpret_cast<const ulonglong2*>(sdbc + (p * CH + t) * XPD);
            ulonglong2 dt01 = rp[0], dt23 = rp[1];
            ull v2 = mul2_(dt01.x, wr2[0]);
            v2 = fma2_(dt01.y, wr2[1], v2);
            v2 = fma2_(dt23.x, wr2[2], v2);
            v2 = fma2_(dt23.y, wr2[3], v2);
            float vlo, vhi; upk2(v2, vlo, vhi);
            float delta = softplus_f(vlo + vhi + bb);
            float u  = up[t * DI];
            float du = delta * u;
            ulonglong2 b01 = rp[2], b23 = rp[3], b45 = rp[4], b67 = rp[5];
            ulonglong2 c01 = rp[6], c23 = rp[7], c45 = rp[8], c67 = rp[9];
            ull B2[8] = {b01.x, b01.y, b23.x, b23.y, b45.x, b45.y, b67.x, b67.y};
            ull C2[8] = {c01.x, c01.y, c23.x, c23.y, c45.x, c45.y, c67.x, c67.y};
            ull y2;
            if (fast) {
                ull a2[8];
                powchain2(__expf(delta * A0), a2);
                ull du2 = pk2(du, du);
                h2[0] = fma2_(a2[0], h2[0], mul2_(du2, B2[0]));
                y2 = mul2_(h2[0], C2[0]);
#pragma unroll
                for (int k = 1; k < 8; k++) {
                    h2[k] = fma2_(a2[k], h2[k], mul2_(du2, B2[k]));
                    y2 = fma2_(h2[k], C2[k], y2);
                }
            } else {
                float ylo = 0.f, yhi = 0.f;
#pragma unroll
                for (int k = 0; k < 8; k++) {
                    float hlo, hhi, blo2, bhi2, clo2, chi2;
                    upk2(h2[k], hlo, hhi); upk2(B2[k], blo2, bhi2);
                    upk2(C2[k], clo2, chi2);
                    hlo = fmaf(__expf(delta * A[2 * k]), hlo, du * blo2);
                    hhi = fmaf(__expf(delta * A[2 * k + 1]), hhi, du * bhi2);
                    h2[k] = pk2(hlo, hhi);
                    ylo = fmaf(hlo, clo2, ylo);
                    yhi = fmaf(hhi, chi2, yhi);
                }
                y2 = pk2(ylo, yhi);
            }
            float ylo, yhi; upk2(y2, ylo, yhi);
            float y = fmaf(u, Dd, ylo + yhi);
            float z  = zp[t * (2 * DI)];
            float sz = z * __fdividef(1.0f, 1.0f + __expf(-z));
            float val = y * sz;
            size_t idx = (size_t)(lp + t) * DI + d;
            __nv_bfloat16 hh, ll; bf16split(val, hh, ll);
            g_yh[idx] = hh; g_yl[idx] = ll;
        }
    }
}

// ---------------- pooled reduce + classifier ----------------
__global__ void k_final(const float* __restrict__ cw, const float* __restrict__ cb,
                        float* __restrict__ out) {
    __shared__ float sp[NB * DM];
    int tid = threadIdx.x;
    for (int idx = tid; idx < NB * DM; idx += 256) {
        int b = idx / DM, m = idx % DM;
        float s = 0.f;
#pragma unroll
        for (int k = 0; k < 16; k++) s += g_poolp[(b * 16 + k) * DM + m];
        sp[idx] = s;
    }
    __syncthreads();
    if (tid < NB * NCLS) {
        int b = tid / NCLS, cc = tid % NCLS;
        float s = 0.f;
#pragma unroll 8
        for (int m = 0; m < DM; m++) s = fmaf(sp[b * DM + m], cw[cc * DM + m], s);
        out[tid] = s * (1.0f / SEQ) + cb[cc];
    }
}

// ---------------- launch ----------------
namespace {
constexpr int SMEM_M0 = 2 * (2 * 128 * 40 * 2 + 2 * 128 * 40 * 2); // 81920
constexpr int SMEM_M1 = 2 * (2 * 128 * 40 * 2 + 2 * 64 * 40 * 2);  // 61440
constexpr int SMEM_M2 = SMEM_M0;  // covers 128*132*4 + 8*128*4 = 71680
}

extern "C" void kernel_launch(void* const* d_in, const int* in_sizes, int n_in,
                              void* d_out, int out_size) {
    const float* x      = (const float*)d_in[0];
    const float* enc_w  = (const float*)d_in[1];
    const float* enc_b  = (const float*)d_in[2];
    const float* norm_w = (const float*)d_in[3];
    const float* in_w   = (const float*)d_in[4];
    const float* conv_w = (const float*)d_in[5];
    const float* conv_b = (const float*)d_in[6];
    const float* xp_w   = (const float*)d_in[7];
    const float* dt_w   = (const float*)d_in[8];
    const float* dt_b   = (const float*)d_in[9];
    const float* A_log  = (const float*)d_in[10];
    const float* Dp     = (const float*)d_in[11];
    const float* out_w  = (const float*)d_in[12];
    const float* nfw    = (const float*)d_in[13];
    const float* cls_w  = (const float*)d_in[14];
    const float* cls_b  = (const float*)d_in[15];
    float* out = (float*)d_out;

    cudaFuncSetAttribute(k_mma<0>, cudaFuncAttributeMaxDynamicSharedMemorySize, SMEM_M0);
    cudaFuncSetAttribute(k_mma<1>, cudaFuncAttributeMaxDynamicSharedMemorySize, SMEM_M1);
    cudaFuncSetAttribute(k_mma<2>, cudaFuncAttributeMaxDynamicSharedMemorySize, SMEM_M2);

    k_cvtw<<<NLAY * 512 * 128 / 256, 256>>>(in_w, xp_w, out_w);
    k_encoder<<<BL, DM>>>(x, enc_w, enc_b, norm_w);   // fused layer-0 rmsnorm

    for (int i = 0; i < NLAY; i++) {
        k_mma<0><<<dim3(BL / 128, 4), 256, SMEM_M0>>>(i, nullptr, nullptr);
        k_conv<<<BL / 4, 256>>>(conv_w + i * DI * 4, conv_b + i * DI);
        k_mma<1><<<dim3(BL / 128, 1), 256, SMEM_M1>>>(i, nullptr, nullptr);
        k_scan<<<SCAN_BLOCKS, DI>>>(A_log + i * DI * DS, Dp + i * DI,
                                    dt_w + i * DI * DTR, dt_b + i * DI);
        k_mma<2><<<dim3(BL / 128, 1), 256, SMEM_M2>>>(
            i,
            (i < NLAY - 1) ? (norm_w + (i + 1) * DM) : nullptr,
            (i == NLAY - 1) ? nfw : nullptr);
    }

    k_final<<<1, 256>>>(cls_w, cls_b, out);
}

// round 14
// speedup vs baseline: 1.4027x; 1.4027x over previous
#include <cuda_runtime.h>
#include <cuda_bf16.h>
#include <math.h>
#include <cstdint>

// ---------------- problem constants ----------------
namespace {
constexpr int NB   = 16;      // batch
constexpr int SEQ  = 2048;    // L
constexpr int DM   = 128;     // d_model
constexpr int DI   = 256;     // d_inner
constexpr int DS   = 16;      // d_state
constexpr int DTR  = 8;       // dt_rank
constexpr int NLAY = 4;
constexpr int NCLS = 5;
constexpr int BL   = NB * SEQ;          // 32768 rows
constexpr int XPD  = DTR + 2 * DS;      // 40
constexpr int NCH  = 32;                // chunks per sequence
constexpr int CH   = SEQ / NCH;         // 64 steps per chunk
constexpr int SCAN_BLOCKS = 256;        // 2 chunks per block; <= co-resident capacity
constexpr float EPS = 1e-5f;
}

typedef unsigned long long ull;

// ---------------- scratch (static __device__, no allocs) ----------------
__device__ float g_h    [BL * DM];            // residual stream
__device__ float g_xz   [BL * 2 * DI];        // in_proj output (xm | z)
__device__ float g_dbc  [BL * XPD];           // x_proj output (dt|B|C)
__device__ float g_P    [NB * NCH * DI * DS];
__device__ float g_S    [NB * NCH * DI * DS];
__device__ float g_H0   [NB * NCH * DI * DS];
__device__ float g_poolp[256 * DM];           // per-mma2-block pool partials

// bf16 activations (single precision-level operands; no hi/lo split)
__device__ __nv_bfloat16 g_xn[BL * DM];       // rmsnorm out
__device__ __nv_bfloat16 g_xc[BL * DI];       // conv+silu out (u) - GEMM & scan input
__device__ __nv_bfloat16 g_y [BL * DI];       // scan out

// bf16 weights, xp padded 40->64 rows with zeros
__device__ __nv_bfloat16 g_wi[NLAY * 512 * 128];
__device__ __nv_bfloat16 g_wx[NLAY * 64 * 256];
__device__ __nv_bfloat16 g_wo[NLAY * 128 * 256];

// global software barrier state (generation-based; monotonic across replays)
__device__ unsigned g_cnt = 0;
__device__ volatile unsigned g_gen = 0;

__device__ __forceinline__ void gbar(unsigned nb) {
    __syncthreads();
    if (threadIdx.x == 0) {
        __threadfence();
        unsigned gen = g_gen;
        if (atomicAdd(&g_cnt, 1u) == nb - 1) {
            atomicExch(&g_cnt, 0u);
            __threadfence();
            g_gen = gen + 1;
        } else {
            while (g_gen == gen) { }
        }
        __threadfence();
    }
    __syncthreads();
}

// ---------------- helpers ----------------
__device__ __forceinline__ uint32_t smem_u32(const void* p) {
    uint32_t a;
    asm("{ .reg .u64 t; cvta.to.shared.u64 t, %1; cvt.u32.u64 %0, t; }"
        : "=r"(a) : "l"(p));
    return a;
}
__device__ __forceinline__ void ldsm4(uint32_t a, uint32_t& r0, uint32_t& r1,
                                      uint32_t& r2, uint32_t& r3) {
    asm volatile("ldmatrix.sync.aligned.m8n8.x4.shared.b16 {%0,%1,%2,%3}, [%4];"
                 : "=r"(r0), "=r"(r1), "=r"(r2), "=r"(r3) : "r"(a));
}
__device__ __forceinline__ void hmma(float* c, const uint32_t* a,
                                     uint32_t b0, uint32_t b1) {
    asm volatile(
        "mma.sync.aligned.m16n8k16.row.col.f32.bf16.bf16.f32 "
        "{%0,%1,%2,%3}, {%4,%5,%6,%7}, {%8,%9}, {%0,%1,%2,%3};"
        : "+f"(c[0]), "+f"(c[1]), "+f"(c[2]), "+f"(c[3])
        : "r"(a[0]), "r"(a[1]), "r"(a[2]), "r"(a[3]), "r"(b0), "r"(b1));
}
__device__ __forceinline__ void cpa16(uint32_t dst, const void* src) {
    asm volatile("cp.async.cg.shared.global [%0], [%1], 16;" :: "r"(dst), "l"(src));
}
__device__ __forceinline__ void cpa_commit() {
    asm volatile("cp.async.commit_group;" ::: "memory");
}
template <int N> __device__ __forceinline__ void cpa_wait() {
    asm volatile("cp.async.wait_group %0;" :: "n"(N) : "memory");
}
// ---- packed f32x2 primitives (lane-exact fp32) ----
__device__ __forceinline__ ull pk2(float lo, float hi) {
    ull r; asm("mov.b64 %0, {%1, %2};" : "=l"(r) : "f"(lo), "f"(hi)); return r;
}
__device__ __forceinline__ void upk2(ull v, float& lo, float& hi) {
    asm("mov.b64 {%0, %1}, %2;" : "=f"(lo), "=f"(hi) : "l"(v));
}
__device__ __forceinline__ ull mul2_(ull a, ull b) {
    ull r; asm("mul.rn.f32x2 %0, %1, %2;" : "=l"(r) : "l"(a), "l"(b)); return r;
}
__device__ __forceinline__ ull fma2_(ull a, ull b, ull c) {
    ull r; asm("fma.rn.f32x2 %0, %1, %2, %3;" : "=l"(r) : "l"(a), "l"(b), "l"(c));
    return r;
}
// packed power ladder: a2[k] = (w^(2k+1), w^(2k+2)), k=0..7
__device__ __forceinline__ void powchain2(float w, ull* a2) {
    float w2 = w * w;
    ull s2 = pk2(w2, w2);
    a2[0] = pk2(w, w2);
#pragma unroll
    for (int k = 1; k < 8; k++) a2[k] = mul2_(a2[k - 1], s2);
}
__device__ __forceinline__ bool a_is_chain(const float* A) {
    bool f = true;
#pragma unroll
    for (int n = 0; n < DS; n++)
        f = f && (fabsf(A[n] - A[0] * (float)(n + 1)) <= 1e-3f * (float)(n + 1));
    return f;
}
__device__ __forceinline__ float softplus_f(float v) {
    return fmaxf(v, 0.0f) + __logf(1.0f + __expf(-fabsf(v)));
}

// ---------------- weight conversion (once per launch) ----------------
__global__ void k_cvtw(const float* __restrict__ in_w,
                       const float* __restrict__ xp_w,
                       const float* __restrict__ out_w) {
    int i = blockIdx.x * 256 + threadIdx.x;
    if (i < NLAY * 512 * 128) g_wi[i] = __float2bfloat16(in_w[i]);
    if (i < NLAY * 64 * 256) {
        int l4 = i / (64 * 256);
        int r  = (i / 256) % 64;
        int c  = i % 256;
        float x = (r < XPD) ? xp_w[((size_t)l4 * XPD + r) * 256 + c] : 0.f;
        g_wx[i] = __float2bfloat16(x);
    }
    if (i < NLAY * 128 * 256) g_wo[i] = __float2bfloat16(out_w[i]);
}

// ---------------- encoder: h = x @ enc_w^T + enc_b, fused layer-0 rmsnorm ----
__global__ void k_encoder(const float* __restrict__ x,
                          const float* __restrict__ ew,
                          const float* __restrict__ eb,
                          const float* __restrict__ nw) {
    int row = blockIdx.x;
    int m   = threadIdx.x;          // 128 threads
    __shared__ float xs[12];
    __shared__ float red[4];
    if (m < 12) xs[m] = x[row * 12 + m];
    __syncthreads();
    float acc = eb[m];
#pragma unroll
    for (int c = 0; c < 12; c++) acc = fmaf(xs[c], ew[m * 12 + c], acc);
    g_h[row * DM + m] = acc;
    float ss = acc * acc;
#pragma unroll
    for (int o = 16; o; o >>= 1) ss += __shfl_xor_sync(0xffffffffu, ss, o);
    if ((m & 31) == 0) red[m >> 5] = ss;
    __syncthreads();
    float tot = red[0] + red[1] + red[2] + red[3];
    float r = rsqrtf(tot * (1.0f / DM) + EPS);
    g_xn[(size_t)row * DM + m] = __float2bfloat16(acc * r * nw[m]);
}

// ---------------- plain-bf16 HMMA GEMM, cp.async 2-stage pipelined ----------
// MODE 0: in_proj  (K=128) -> g_xz  (N=512, grid.y=4)
// MODE 1: x_proj   (K=256) -> g_dbc (N=40 real, TN=64)
// MODE 2: out_proj (K=256) -> g_h   (accumulate) + fused next-rmsnorm (nwp)
//         or fused final rmsnorm+pool partials (poolw) on the last layer.
template <int MODE>
__global__ void __launch_bounds__(256, 2) k_mma(int layer,
                                                const float* __restrict__ nwp,
                                                const float* __restrict__ poolw) {
    constexpr int K   = (MODE == 0) ? 128 : 256;
    constexpr int TN  = (MODE == 1) ? 64 : 128;
    constexpr int NF  = TN / 16;
    constexpr bool ACC = (MODE == 2);
    constexpr int STR = 40;                       // smem row stride (bf16)
    constexpr int NC  = K / 32;                   // k-chunks
    constexpr int ASZ = 128 * STR * 2;            // bytes per A tile
    constexpr int BSZ = TN * STR * 2;             // bytes per B tile
    constexpr int STG = ASZ + BSZ;                // bytes per stage
    constexpr int CTSTR = 132;                    // fp32 epilogue tile stride

    extern __shared__ __align__(16) char sm[];

    const __nv_bfloat16* Ag = (MODE == 0) ? g_xn : (MODE == 1 ? g_xc : g_y);
    const __nv_bfloat16* W;
    if (MODE == 0)      W = g_wi + (size_t)layer * 512 * 128;
    else if (MODE == 1) W = g_wx + (size_t)layer * 64 * 256;
    else                W = g_wo + (size_t)layer * 128 * 256;
    float* C  = (MODE == 0) ? g_xz : (MODE == 1 ? g_dbc : g_h);
    const int ldC = (MODE == 0) ? 512 : (MODE == 1 ? XPD : DM);

    const int tid = threadIdx.x;
    const int lid = tid & 31;
    const int wid = tid >> 5;
    const int mw  = wid & 3;
    const int nw  = wid >> 2;
    const int bm  = blockIdx.x * 128;
    const int bn  = blockIdx.y * TN;
    const int rb0 = mw * 32;
    const int nb0 = nw * (TN / 2);

    const uint32_t sb0 = smem_u32(sm);

    auto stage_fn = [&](int kc, int st) {
        uint32_t base = sb0 + (uint32_t)st * STG;
#pragma unroll
        for (int s = tid; s < 512; s += 256) {
            int row = s >> 2, c8 = (s & 3) * 8;
            size_t go = (size_t)(bm + row) * K + kc * 32 + c8;
            cpa16(base + (uint32_t)(row * STR + c8) * 2, Ag + go);
        }
#pragma unroll
        for (int s = tid; s < TN * 4; s += 256) {
            int row = s >> 2, c8 = (s & 3) * 8;
            size_t go = (size_t)(bn + row) * K + kc * 32 + c8;
            cpa16(base + ASZ + (uint32_t)(row * STR + c8) * 2, W + go);
        }
        cpa_commit();
    };

    const int arow = (lid & 7) + ((lid >> 3) & 1) * 8;
    const int acol = (lid >> 4) * 8;
    const int brow = (lid & 7) + ((lid >> 3) >= 2 ? 8 : 0);
    const int bcol = ((lid >> 3) & 1) * 8;

    float acc[2][NF][4];
#pragma unroll
    for (int mi = 0; mi < 2; mi++)
#pragma unroll
        for (int ni = 0; ni < NF; ni++)
#pragma unroll
            for (int q = 0; q < 4; q++) acc[mi][ni][q] = 0.f;

    stage_fn(0, 0);
    if (NC > 1) stage_fn(1, 1);

    for (int kc = 0; kc < NC; kc++) {
        if (kc + 1 < NC) cpa_wait<1>(); else cpa_wait<0>();
        __syncthreads();
        uint32_t base = sb0 + (uint32_t)(kc & 1) * STG;
        uint32_t bA = base, bB = base + ASZ;
#pragma unroll
        for (int ks = 0; ks < 32; ks += 16) {
            uint32_t af[2][4];
#pragma unroll
            for (int mi = 0; mi < 2; mi++) {
                uint32_t aoff =
                    (uint32_t)(((rb0 + mi * 16 + arow) * STR + ks + acol) * 2);
                ldsm4(bA + aoff, af[mi][0], af[mi][1], af[mi][2], af[mi][3]);
            }
            uint32_t bf[NF][2];
#pragma unroll
            for (int nj = 0; nj < NF / 2; nj++) {
                uint32_t r0, r1, r2, r3;
                uint32_t boff =
                    (uint32_t)(((nb0 + nj * 16 + brow) * STR + ks + bcol) * 2);
                ldsm4(bB + boff, r0, r1, r2, r3);
                bf[nj * 2][0] = r0; bf[nj * 2][1] = r1;
                bf[nj * 2 + 1][0] = r2; bf[nj * 2 + 1][1] = r3;
            }
#pragma unroll
            for (int mi = 0; mi < 2; mi++)
#pragma unroll
                for (int ni = 0; ni < NF; ni++)
                    hmma(acc[mi][ni], af[mi], bf[ni][0], bf[ni][1]);
        }
        __syncthreads();
        if (kc + 2 < NC) stage_fn(kc + 2, kc & 1);
    }

    // epilogue
    float* ct = reinterpret_cast<float*>(sm);   // fp32 tile for MODE 2 fusion
    const int g = lid >> 2, t = lid & 3;
#pragma unroll
    for (int mi = 0; mi < 2; mi++) {
        int row0 = bm + rb0 + mi * 16 + g;
#pragma unroll
        for (int ni = 0; ni < NF; ni++) {
            int col = bn + nb0 + ni * 8 + t * 2;
            if (MODE == 1 && col >= XPD) continue;
            float2* p0 = reinterpret_cast<float2*>(C + (size_t)row0 * ldC + col);
            float2* p1 = reinterpret_cast<float2*>(C + (size_t)(row0 + 8) * ldC + col);
            float2 v0 = make_float2(acc[mi][ni][0], acc[mi][ni][1]);
            float2 v1 = make_float2(acc[mi][ni][2], acc[mi][ni][3]);
            if (ACC) {
                float2 o0 = *p0, o1 = *p1;
                v0.x += o0.x; v0.y += o0.y; v1.x += o1.x; v1.y += o1.y;
            }
            *p0 = v0; *p1 = v1;
            if (MODE == 2) {
                int lr0 = rb0 + mi * 16 + g;
                ct[lr0 * CTSTR + col] = v0.x; ct[lr0 * CTSTR + col + 1] = v0.y;
                ct[(lr0 + 8) * CTSTR + col] = v1.x; ct[(lr0 + 8) * CTSTR + col + 1] = v1.y;
            }
        }
    }
    if (MODE == 2 && nwp != nullptr) {
        __syncthreads();
        float4 wv = reinterpret_cast<const float4*>(nwp)[lid];
#pragma unroll 4
        for (int rr = 0; rr < 16; rr++) {
            int lr = wid * 16 + rr;
            float4 v = *reinterpret_cast<const float4*>(ct + lr * CTSTR + lid * 4);
            float ss = v.x * v.x + v.y * v.y + v.z * v.z + v.w * v.w;
#pragma unroll
            for (int o = 16; o; o >>= 1) ss += __shfl_xor_sync(0xffffffffu, ss, o);
            float rn = rsqrtf(ss * (1.0f / DM) + EPS);
            __nv_bfloat162 a01 = __nv_bfloat162(__float2bfloat16(v.x * rn * wv.x),
                                                __float2bfloat16(v.y * rn * wv.y));
            __nv_bfloat162 a23 = __nv_bfloat162(__float2bfloat16(v.z * rn * wv.z),
                                                __float2bfloat16(v.w * rn * wv.w));
            size_t base = (size_t)(bm + lr) * DM + lid * 4;
            *reinterpret_cast<__nv_bfloat162*>(g_xn + base)     = a01;
            *reinterpret_cast<__nv_bfloat162*>(g_xn + base + 2) = a23;
        }
    }
    if (MODE == 2 && poolw != nullptr) {
        __syncthreads();
        float* spool = reinterpret_cast<float*>(sm + 128 * CTSTR * 4);  // [8][128]
        float4 wv = reinterpret_cast<const float4*>(poolw)[lid];
        float pa0 = 0.f, pa1 = 0.f, pa2 = 0.f, pa3 = 0.f;
#pragma unroll 4
        for (int rr = 0; rr < 16; rr++) {
            int lr = wid * 16 + rr;
            float4 v = *reinterpret_cast<const float4*>(ct + lr * CTSTR + lid * 4);
            float ss = v.x * v.x + v.y * v.y + v.z * v.z + v.w * v.w;
#pragma unroll
            for (int o = 16; o; o >>= 1) ss += __shfl_xor_sync(0xffffffffu, ss, o);
            float rn = rsqrtf(ss * (1.0f / DM) + EPS);
            pa0 = fmaf(v.x * rn, wv.x, pa0);
            pa1 = fmaf(v.y * rn, wv.y, pa1);
            pa2 = fmaf(v.z * rn, wv.z, pa2);
            pa3 = fmaf(v.w * rn, wv.w, pa3);
        }
        __syncthreads();
        spool[wid * DM + lid * 4 + 0] = pa0;
        spool[wid * DM + lid * 4 + 1] = pa1;
        spool[wid * DM + lid * 4 + 2] = pa2;
        spool[wid * DM + lid * 4 + 3] = pa3;
        __syncthreads();
        if (tid < DM) {
            float s = 0.f;
#pragma unroll
            for (int w = 0; w < 8; w++) s += spool[w * DM + tid];
            g_poolp[blockIdx.x * DM + tid] = s;
        }
    }
}

// ---------------- causal depthwise conv + silu -> bf16 u --------------------
__global__ void k_conv(const float* __restrict__ cw, const float* __restrict__ cb) {
    int d   = threadIdx.x;               // 0..255
    int bl0 = blockIdx.x * 4;            // 4 consecutive rows, same sequence
    int l   = bl0 & (SEQ - 1);
    const float* src = g_xz + (size_t)bl0 * (2 * DI) + d;
    float w0 = cw[d * 4 + 0], w1 = cw[d * 4 + 1], w2 = cw[d * 4 + 2], w3 = cw[d * 4 + 3];
    float b  = cb[d];
    float v0, v1, v2;
    if (l == 0) { v0 = v1 = v2 = 0.f; }
    else { v0 = src[-3 * 512]; v1 = src[-2 * 512]; v2 = src[-512]; }
    float v3 = src[0], v4 = src[512], v5 = src[2 * 512], v6 = src[3 * 512];
    float va[7] = {v0, v1, v2, v3, v4, v5, v6};
#pragma unroll
    for (int j = 0; j < 4; j++) {
        float s = b;
        s = fmaf(va[j + 0], w0, s);
        s = fmaf(va[j + 1], w1, s);
        s = fmaf(va[j + 2], w2, s);
        s = fmaf(va[j + 3], w3, s);
        float sig = __fdividef(1.0f, 1.0f + __expf(-s));
        g_xc[(size_t)(bl0 + j) * DI + d] = __float2bfloat16(s * sig);
    }
}

// ---------------- fused selective scan (packed f32x2 math) ------------------
// Grid = 256 blocks (one per (b, chunk-pair)), 256 threads (= d).
// __launch_bounds__(256, 2) -> >=2 CTAs/SM -> all blocks co-resident (barrier-safe).
__global__ void __launch_bounds__(256, 2) k_scan(
        const float* __restrict__ Alog, const float* __restrict__ Dpl,
        const float* __restrict__ dtw,  const float* __restrict__ dtb) {
    __shared__ float sdbc[2 * CH * XPD];    // 2 chunks x 64 x 40 floats = 20KB
    const int d  = threadIdx.x;
    const int b  = blockIdx.x >> 4;
    const int cc = blockIdx.x & 15;
    const int c0 = cc * 2;
    const int l0 = b * SEQ + c0 * CH;

    for (int s = d; s < 2 * CH * (XPD / 4); s += DI) {
        reinterpret_cast<float4*>(sdbc)[s] =
            *reinterpret_cast<const float4*>(g_dbc + (size_t)l0 * XPD + s * 4);
    }
    __syncthreads();

    float A[DS];
#pragma unroll
    for (int n = 0; n < DS; n++) A[n] = -__expf(Alog[d * DS + n]);
    const bool fast = a_is_chain(A);
    const float A0 = A[0];
    ull wr2[4];
#pragma unroll
    for (int k = 0; k < 4; k++)
        wr2[k] = pk2(dtw[d * DTR + 2 * k], dtw[d * DTR + 2 * k + 1]);
    const float bb = dtb[d];
    const float Dd = Dpl[d];

    // ---- phase A: local chunk scans -> P, S ----
#pragma unroll
    for (int p = 0; p < 2; p++) {
        const __nv_bfloat16* up = g_xc + (size_t)(l0 + p * CH) * DI + d;
        ull S2[8];
#pragma unroll
        for (int k = 0; k < 8; k++) S2[k] = 0ull;
        float dsum = 0.f;
        for (int t = 0; t < CH; t++) {
            const ulonglong2* rp =
                reinterpret_cast<const ulonglong2*>(sdbc + (p * CH + t) * XPD);
            ulonglong2 dt01 = rp[0], dt23 = rp[1];
            ull v2 = mul2_(dt01.x, wr2[0]);
            v2 = fma2_(dt01.y, wr2[1], v2);
            v2 = fma2_(dt23.x, wr2[2], v2);
            v2 = fma2_(dt23.y, wr2[3], v2);
            float vlo, vhi; upk2(v2, vlo, vhi);
            float delta = softplus_f(vlo + vhi + bb);
            float du = delta * __bfloat162float(up[t * DI]);
            dsum += delta;
            ulonglong2 b01 = rp[2], b23 = rp[3], b45 = rp[4], b67 = rp[5];
            ull B2[8] = {b01.x, b01.y, b23.x, b23.y, b45.x, b45.y, b67.x, b67.y};
            if (fast) {
                ull a2[8];
                powchain2(__expf(delta * A0), a2);
                ull du2 = pk2(du, du);
#pragma unroll
                for (int k = 0; k < 8; k++)
                    S2[k] = fma2_(a2[k], S2[k], mul2_(du2, B2[k]));
            } else {
#pragma unroll
                for (int k = 0; k < 8; k++) {
                    float slo, shi, blo2, bhi2;
                    upk2(S2[k], slo, shi); upk2(B2[k], blo2, bhi2);
                    slo = fmaf(__expf(delta * A[2 * k]), slo, du * blo2);
                    shi = fmaf(__expf(delta * A[2 * k + 1]), shi, du * bhi2);
                    S2[k] = pk2(slo, shi);
                }
            }
        }
        int o = (((b * NCH + c0 + p) * DI) + d) * DS;
        ull P2[8];
        if (fast) {
            powchain2(__expf(dsum * A0), P2);
        } else {
#pragma unroll
            for (int k = 0; k < 8; k++)
                P2[k] = pk2(__expf(A[2 * k] * dsum), __expf(A[2 * k + 1] * dsum));
        }
        ulonglong2* Pp = reinterpret_cast<ulonglong2*>(g_P + o);
        ulonglong2* Sp = reinterpret_cast<ulonglong2*>(g_S + o);
#pragma unroll
        for (int q = 0; q < 4; q++) {
            Pp[q] = make_ulonglong2(P2[2 * q], P2[2 * q + 1]);
            Sp[q] = make_ulonglong2(S2[2 * q], S2[2 * q + 1]);
        }
    }

    // ---- phase B: chunk-boundary recurrence ----
    gbar(SCAN_BLOCKS);
    {
        int item = blockIdx.x * 256 + d;
        int bb2 = item >> 12;
        int dn  = item & 4095;
        float h = 0.f;
        for (int c = 0; c < NCH; c++) {
            int o = (bb2 * NCH + c) * DI * DS + dn;
            g_H0[o] = h;
            h = fmaf(g_P[o], h, g_S[o]);
        }
    }
    gbar(SCAN_BLOCKS);

    // ---- phase C: corrected replay -> y (bf16) ----
#pragma unroll
    for (int p = 0; p < 2; p++) {
        ull h2[8];
        {
            int o = (((b * NCH + c0 + p) * DI) + d) * DS;
            const ulonglong2* Hp = reinterpret_cast<const ulonglong2*>(g_H0 + o);
#pragma unroll
            for (int q = 0; q < 4; q++) {
                ulonglong2 hv = Hp[q];
                h2[2 * q] = hv.x; h2[2 * q + 1] = hv.y;
            }
        }
        const int lp = l0 + p * CH;
        const __nv_bfloat16* up = g_xc + (size_t)lp * DI + d;
        const float* zp = g_xz + (size_t)lp * (2 * DI) + DI + d;
        for (int t = 0; t < CH; t++) {
            const ulonglong2* rp =
                reinterpret_cast<const ulonglong2*>(sdbc + (p * CH + t) * XPD);
            ulonglong2 dt01 = rp[0], dt23 = rp[1];
            ull v2 = mul2_(dt01.x, wr2[0]);
            v2 = fma2_(dt01.y, wr2[1], v2);
            v2 = fma2_(dt23.x, wr2[2], v2);
            v2 = fma2_(dt23.y, wr2[3], v2);
            float vlo, vhi; upk2(v2, vlo, vhi);
            float delta = softplus_f(vlo + vhi + bb);
            float u  = __bfloat162float(up[t * DI]);
            float du = delta * u;
            ulonglong2 b01 = rp[2], b23 = rp[3], b45 = rp[4], b67 = rp[5];
            ulonglong2 c01 = rp[6], c23 = rp[7], c45 = rp[8], c67 = rp[9];
            ull B2[8] = {b01.x, b01.y, b23.x, b23.y, b45.x, b45.y, b67.x, b67.y};
            ull C2[8] = {c01.x, c01.y, c23.x, c23.y, c45.x, c45.y, c67.x, c67.y};
            ull y2;
            if (fast) {
                ull a2[8];
                powchain2(__expf(delta * A0), a2);
                ull du2 = pk2(du, du);
                h2[0] = fma2_(a2[0], h2[0], mul2_(du2, B2[0]));
                y2 = mul2_(h2[0], C2[0]);
#pragma unroll
                for (int k = 1; k < 8; k++) {
                    h2[k] = fma2_(a2[k], h2[k], mul2_(du2, B2[k]));
                    y2 = fma2_(h2[k], C2[k], y2);
                }
            } else {
                float ylo = 0.f, yhi = 0.f;
#pragma unroll
                for (int k = 0; k < 8; k++) {
                    float hlo, hhi, blo2, bhi2, clo2, chi2;
                    upk2(h2[k], hlo, hhi); upk2(B2[k], blo2, bhi2);
                    upk2(C2[k], clo2, chi2);
                    hlo = fmaf(__expf(delta * A[2 * k]), hlo, du * blo2);
                    hhi = fmaf(__expf(delta * A[2 * k + 1]), hhi, du * bhi2);
                    h2[k] = pk2(hlo, hhi);
                    ylo = fmaf(hlo, clo2, ylo);
                    yhi = fmaf(hhi, chi2, yhi);
                }
                y2 = pk2(ylo, yhi);
            }
            float ylo, yhi; upk2(y2, ylo, yhi);
            float y = fmaf(u, Dd, ylo + yhi);
            float z  = zp[t * (2 * DI)];
            float sz = z * __fdividef(1.0f, 1.0f + __expf(-z));
            g_y[(size_t)(lp + t) * DI + d] = __float2bfloat16(y * sz);
        }
    }
}

// ---------------- pooled reduce + classifier ----------------
__global__ void k_final(const float* __restrict__ cw, const float* __restrict__ cb,
                        float* __restrict__ out) {
    __shared__ float sp[NB * DM];
    int tid = threadIdx.x;
    for (int idx = tid; idx < NB * DM; idx += 256) {
        int b = idx / DM, m = idx % DM;
        float s = 0.f;
#pragma unroll
        for (int k = 0; k < 16; k++) s += g_poolp[(b * 16 + k) * DM + m];
        sp[idx] = s;
    }
    __syncthreads();
    if (tid < NB * NCLS) {
        int b = tid / NCLS, cc = tid % NCLS;
        float s = 0.f;
#pragma unroll 8
        for (int m = 0; m < DM; m++) s = fmaf(sp[b * DM + m], cw[cc * DM + m], s);
        out[tid] = s * (1.0f / SEQ) + cb[cc];
    }
}

// ---------------- launch ----------------
namespace {
constexpr int SMEM_M0 = 2 * (128 * 40 * 2 + 128 * 40 * 2);  // 40960
constexpr int SMEM_M1 = 2 * (128 * 40 * 2 + 64 * 40 * 2);   // 30720
constexpr int SMEM_M2 = 128 * 132 * 4 + 8 * 128 * 4;        // 71680 (epilogue tile)
}

extern "C" void kernel_launch(void* const* d_in, const int* in_sizes, int n_in,
                              void* d_out, int out_size) {
    const float* x      = (const float*)d_in[0];
    const float* enc_w  = (const float*)d_in[1];
    const float* enc_b  = (const float*)d_in[2];
    const float* norm_w = (const float*)d_in[3];
    const float* in_w   = (const float*)d_in[4];
    const float* conv_w = (const float*)d_in[5];
    const float* conv_b = (const float*)d_in[6];
    const float* xp_w   = (const float*)d_in[7];
    const float* dt_w   = (const float*)d_in[8];
    const float* dt_b   = (const float*)d_in[9];
    const float* A_log  = (const float*)d_in[10];
    const float* Dp     = (const float*)d_in[11];
    const float* out_w  = (const float*)d_in[12];
    const float* nfw    = (const float*)d_in[13];
    const float* cls_w  = (const float*)d_in[14];
    const float* cls_b  = (const float*)d_in[15];
    float* out = (float*)d_out;

    cudaFuncSetAttribute(k_mma<0>, cudaFuncAttributeMaxDynamicSharedMemorySize, SMEM_M0);
    cudaFuncSetAttribute(k_mma<1>, cudaFuncAttributeMaxDynamicSharedMemorySize, SMEM_M1);
    cudaFuncSetAttribute(k_mma<2>, cudaFuncAttributeMaxDynamicSharedMemorySize, SMEM_M2);

    k_cvtw<<<NLAY * 512 * 128 / 256, 256>>>(in_w, xp_w, out_w);
    k_encoder<<<BL, DM>>>(x, enc_w, enc_b, norm_w);   // fused layer-0 rmsnorm

    for (int i = 0; i < NLAY; i++) {
        k_mma<0><<<dim3(BL / 128, 4), 256, SMEM_M0>>>(i, nullptr, nullptr);
        k_conv<<<BL / 4, 256>>>(conv_w + i * DI * 4, conv_b + i * DI);
        k_mma<1><<<dim3(BL / 128, 1), 256, SMEM_M1>>>(i, nullptr, nullptr);
        k_scan<<<SCAN_BLOCKS, DI>>>(A_log + i * DI * DS, Dp + i * DI,
                                    dt_w + i * DI * DTR, dt_b + i * DI);
        k_mma<2><<<dim3(BL / 128, 1), 256, SMEM_M2>>>(
            i,
            (i < NLAY - 1) ? (norm_w + (i + 1) * DM) : nullptr,
            (i == NLAY - 1) ? nfw : nullptr);
    }

    k_final<<<1, 256>>>(cls_w, cls_b, out);
}

// round 15
// speedup vs baseline: 1.4978x; 1.0678x over previous
#include <cuda_runtime.h>
#include <cuda_bf16.h>
#include <math.h>
#include <cstdint>

// ---------------- problem constants ----------------
namespace {
constexpr int NB   = 16;      // batch
constexpr int SEQ  = 2048;    // L
constexpr int DM   = 128;     // d_model
constexpr int DI   = 256;     // d_inner
constexpr int DS   = 16;      // d_state
constexpr int DTR  = 8;       // dt_rank
constexpr int NLAY = 4;
constexpr int NCLS = 5;
constexpr int BL   = NB * SEQ;          // 32768 rows
constexpr int XPD  = DTR + 2 * DS;      // 40
constexpr int NCH  = 32;                // chunks per sequence
constexpr int CH   = SEQ / NCH;         // 64 steps per chunk
constexpr int SCAN_BLOCKS = 256;        // 2 chunks per block; <= co-resident capacity
constexpr float EPS = 1e-5f;
}

typedef unsigned long long ull;

// ---------------- scratch (static __device__, no allocs) ----------------
__device__ float g_h    [BL * DM];            // residual stream
__device__ float g_dbc  [BL * XPD];           // x_proj output (dt|B|C)
__device__ float g_P    [NB * NCH * DI * DS];
__device__ float g_S    [NB * NCH * DI * DS];
__device__ float g_H0   [NB * NCH * DI * DS];
__device__ float g_poolp[256 * DM];           // per-mma2-block pool partials

// bf16 activations
__device__ __nv_bfloat16 g_xn[BL * DM];       // rmsnorm out
__device__ __nv_bfloat16 g_xm[BL * DI];       // in_proj xm half (conv input)
__device__ __nv_bfloat16 g_z [BL * DI];       // in_proj z half (gate)
__device__ __nv_bfloat16 g_xc[BL * DI];       // conv+silu out (u) - GEMM & scan input
__device__ __nv_bfloat16 g_y [BL * DI];       // scan out

// bf16 weights, xp padded 40->64 rows with zeros
__device__ __nv_bfloat16 g_wi[NLAY * 512 * 128];
__device__ __nv_bfloat16 g_wx[NLAY * 64 * 256];
__device__ __nv_bfloat16 g_wo[NLAY * 128 * 256];

// global software barrier state (generation-based; monotonic across replays)
__device__ unsigned g_cnt = 0;
__device__ volatile unsigned g_gen = 0;

__device__ __forceinline__ void gbar(unsigned nb) {
    __syncthreads();
    if (threadIdx.x == 0) {
        __threadfence();
        unsigned gen = g_gen;
        if (atomicAdd(&g_cnt, 1u) == nb - 1) {
            atomicExch(&g_cnt, 0u);
            __threadfence();
            g_gen = gen + 1;
        } else {
            while (g_gen == gen) { }
        }
        __threadfence();
    }
    __syncthreads();
}

// ---------------- helpers ----------------
__device__ __forceinline__ uint32_t smem_u32(const void* p) {
    uint32_t a;
    asm("{ .reg .u64 t; cvta.to.shared.u64 t, %1; cvt.u32.u64 %0, t; }"
        : "=r"(a) : "l"(p));
    return a;
}
__device__ __forceinline__ void ldsm4(uint32_t a, uint32_t& r0, uint32_t& r1,
                                      uint32_t& r2, uint32_t& r3) {
    asm volatile("ldmatrix.sync.aligned.m8n8.x4.shared.b16 {%0,%1,%2,%3}, [%4];"
                 : "=r"(r0), "=r"(r1), "=r"(r2), "=r"(r3) : "r"(a));
}
__device__ __forceinline__ void hmma(float* c, const uint32_t* a,
                                     uint32_t b0, uint32_t b1) {
    asm volatile(
        "mma.sync.aligned.m16n8k16.row.col.f32.bf16.bf16.f32 "
        "{%0,%1,%2,%3}, {%4,%5,%6,%7}, {%8,%9}, {%0,%1,%2,%3};"
        : "+f"(c[0]), "+f"(c[1]), "+f"(c[2]), "+f"(c[3])
        : "r"(a[0]), "r"(a[1]), "r"(a[2]), "r"(a[3]), "r"(b0), "r"(b1));
}
__device__ __forceinline__ void cpa16(uint32_t dst, const void* src) {
    asm volatile("cp.async.cg.shared.global [%0], [%1], 16;" :: "r"(dst), "l"(src));
}
__device__ __forceinline__ void cpa_commit() {
    asm volatile("cp.async.commit_group;" ::: "memory");
}
template <int N> __device__ __forceinline__ void cpa_wait() {
    asm volatile("cp.async.wait_group %0;" :: "n"(N) : "memory");
}
// ---- packed f32x2 primitives (lane-exact fp32) ----
__device__ __forceinline__ ull pk2(float lo, float hi) {
    ull r; asm("mov.b64 %0, {%1, %2};" : "=l"(r) : "f"(lo), "f"(hi)); return r;
}
__device__ __forceinline__ void upk2(ull v, float& lo, float& hi) {
    asm("mov.b64 {%0, %1}, %2;" : "=f"(lo), "=f"(hi) : "l"(v));
}
__device__ __forceinline__ ull mul2_(ull a, ull b) {
    ull r; asm("mul.rn.f32x2 %0, %1, %2;" : "=l"(r) : "l"(a), "l"(b)); return r;
}
__device__ __forceinline__ ull fma2_(ull a, ull b, ull c) {
    ull r; asm("fma.rn.f32x2 %0, %1, %2, %3;" : "=l"(r) : "l"(a), "l"(b), "l"(c));
    return r;
}
// packed power ladder: a2[k] = (w^(2k+1), w^(2k+2)), k=0..7
__device__ __forceinline__ void powchain2(float w, ull* a2) {
    float w2 = w * w;
    ull s2 = pk2(w2, w2);
    a2[0] = pk2(w, w2);
#pragma unroll
    for (int k = 1; k < 8; k++) a2[k] = mul2_(a2[k - 1], s2);
}
__device__ __forceinline__ bool a_is_chain(const float* A) {
    bool f = true;
#pragma unroll
    for (int n = 0; n < DS; n++)
        f = f && (fabsf(A[n] - A[0] * (float)(n + 1)) <= 1e-3f * (float)(n + 1));
    return f;
}
__device__ __forceinline__ float softplus_f(float v) {
    return fmaxf(v, 0.0f) + __logf(1.0f + __expf(-fabsf(v)));
}

// ---------------- weight conversion (once per launch) ----------------
__global__ void k_cvtw(const float* __restrict__ in_w,
                       const float* __restrict__ xp_w,
                       const float* __restrict__ out_w) {
    int i = blockIdx.x * 256 + threadIdx.x;
    if (i < NLAY * 512 * 128) g_wi[i] = __float2bfloat16(in_w[i]);
    if (i < NLAY * 64 * 256) {
        int l4 = i / (64 * 256);
        int r  = (i / 256) % 64;
        int c  = i % 256;
        float x = (r < XPD) ? xp_w[((size_t)l4 * XPD + r) * 256 + c] : 0.f;
        g_wx[i] = __float2bfloat16(x);
    }
    if (i < NLAY * 128 * 256) g_wo[i] = __float2bfloat16(out_w[i]);
}

// ---------------- encoder: h = x @ enc_w^T + enc_b, fused layer-0 rmsnorm ----
__global__ void k_encoder(const float* __restrict__ x,
                          const float* __restrict__ ew,
                          const float* __restrict__ eb,
                          const float* __restrict__ nw) {
    int row = blockIdx.x;
    int m   = threadIdx.x;          // 128 threads
    __shared__ float xs[12];
    __shared__ float red[4];
    if (m < 12) xs[m] = x[row * 12 + m];
    __syncthreads();
    float acc = eb[m];
#pragma unroll
    for (int c = 0; c < 12; c++) acc = fmaf(xs[c], ew[m * 12 + c], acc);
    g_h[row * DM + m] = acc;
    float ss = acc * acc;
#pragma unroll
    for (int o = 16; o; o >>= 1) ss += __shfl_xor_sync(0xffffffffu, ss, o);
    if ((m & 31) == 0) red[m >> 5] = ss;
    __syncthreads();
    float tot = red[0] + red[1] + red[2] + red[3];
    float r = rsqrtf(tot * (1.0f / DM) + EPS);
    g_xn[(size_t)row * DM + m] = __float2bfloat16(acc * r * nw[m]);
}

// ---------------- plain-bf16 HMMA GEMM, cp.async 2-stage pipelined ----------
// MODE 0: in_proj  (K=128) -> bf16 g_xm / g_z (N=512, grid.y=4; block fully in one half)
// MODE 1: x_proj   (K=256) -> g_dbc (N=40 real, TN=64)
// MODE 2: out_proj (K=256) -> g_h   (accumulate) + fused next-rmsnorm (nwp)
//         or fused final rmsnorm+pool partials (poolw) on the last layer.
template <int MODE>
__global__ void __launch_bounds__(256, 2) k_mma(int layer,
                                                const float* __restrict__ nwp,
                                                const float* __restrict__ poolw) {
    constexpr int K   = (MODE == 0) ? 128 : 256;
    constexpr int TN  = (MODE == 1) ? 64 : 128;
    constexpr int NF  = TN / 16;
    constexpr bool ACC = (MODE == 2);
    constexpr int STR = 40;                       // smem row stride (bf16)
    constexpr int NC  = K / 32;                   // k-chunks
    constexpr int ASZ = 128 * STR * 2;            // bytes per A tile
    constexpr int BSZ = TN * STR * 2;             // bytes per B tile
    constexpr int STG = ASZ + BSZ;                // bytes per stage
    constexpr int CTSTR = 132;                    // fp32 epilogue tile stride

    extern __shared__ __align__(16) char sm[];

    const __nv_bfloat16* Ag = (MODE == 0) ? g_xn : (MODE == 1 ? g_xc : g_y);
    const __nv_bfloat16* W;
    if (MODE == 0)      W = g_wi + (size_t)layer * 512 * 128;
    else if (MODE == 1) W = g_wx + (size_t)layer * 64 * 256;
    else                W = g_wo + (size_t)layer * 128 * 256;
    float* C  = (MODE == 1) ? g_dbc : g_h;
    const int ldC = (MODE == 1) ? XPD : DM;

    const int tid = threadIdx.x;
    const int lid = tid & 31;
    const int wid = tid >> 5;
    const int mw  = wid & 3;
    const int nw  = wid >> 2;
    const int bm  = blockIdx.x * 128;
    const int bn  = blockIdx.y * TN;
    const int rb0 = mw * 32;
    const int nb0 = nw * (TN / 2);

    // MODE 0: block writes wholly into xm (bn<256) or z (bn>=256)
    __nv_bfloat16* Cb = nullptr;
    int bnb = 0;
    if (MODE == 0) { Cb = (bn < DI) ? g_xm : g_z; bnb = bn & (DI - 1); }

    const uint32_t sb0 = smem_u32(sm);

    auto stage_fn = [&](int kc, int st) {
        uint32_t base = sb0 + (uint32_t)st * STG;
#pragma unroll
        for (int s = tid; s < 512; s += 256) {
            int row = s >> 2, c8 = (s & 3) * 8;
            size_t go = (size_t)(bm + row) * K + kc * 32 + c8;
            cpa16(base + (uint32_t)(row * STR + c8) * 2, Ag + go);
        }
#pragma unroll
        for (int s = tid; s < TN * 4; s += 256) {
            int row = s >> 2, c8 = (s & 3) * 8;
            size_t go = (size_t)(bn + row) * K + kc * 32 + c8;
            cpa16(base + ASZ + (uint32_t)(row * STR + c8) * 2, W + go);
        }
        cpa_commit();
    };

    const int arow = (lid & 7) + ((lid >> 3) & 1) * 8;
    const int acol = (lid >> 4) * 8;
    const int brow = (lid & 7) + ((lid >> 3) >= 2 ? 8 : 0);
    const int bcol = ((lid >> 3) & 1) * 8;

    float acc[2][NF][4];
#pragma unroll
    for (int mi = 0; mi < 2; mi++)
#pragma unroll
        for (int ni = 0; ni < NF; ni++)
#pragma unroll
            for (int q = 0; q < 4; q++) acc[mi][ni][q] = 0.f;

    stage_fn(0, 0);
    if (NC > 1) stage_fn(1, 1);

    for (int kc = 0; kc < NC; kc++) {
        if (kc + 1 < NC) cpa_wait<1>(); else cpa_wait<0>();
        __syncthreads();
        uint32_t base = sb0 + (uint32_t)(kc & 1) * STG;
        uint32_t bA = base, bB = base + ASZ;
#pragma unroll
        for (int ks = 0; ks < 32; ks += 16) {
            uint32_t af[2][4];
#pragma unroll
            for (int mi = 0; mi < 2; mi++) {
                uint32_t aoff =
                    (uint32_t)(((rb0 + mi * 16 + arow) * STR + ks + acol) * 2);
                ldsm4(bA + aoff, af[mi][0], af[mi][1], af[mi][2], af[mi][3]);
            }
            uint32_t bf[NF][2];
#pragma unroll
            for (int nj = 0; nj < NF / 2; nj++) {
                uint32_t r0, r1, r2, r3;
                uint32_t boff =
                    (uint32_t)(((nb0 + nj * 16 + brow) * STR + ks + bcol) * 2);
                ldsm4(bB + boff, r0, r1, r2, r3);
                bf[nj * 2][0] = r0; bf[nj * 2][1] = r1;
                bf[nj * 2 + 1][0] = r2; bf[nj * 2 + 1][1] = r3;
            }
#pragma unroll
            for (int mi = 0; mi < 2; mi++)
#pragma unroll
                for (int ni = 0; ni < NF; ni++)
                    hmma(acc[mi][ni], af[mi], bf[ni][0], bf[ni][1]);
        }
        __syncthreads();
        if (kc + 2 < NC) stage_fn(kc + 2, kc & 1);
    }

    // epilogue
    float* ct = reinterpret_cast<float*>(sm);   // fp32 tile for MODE 2 fusion
    const int g = lid >> 2, t = lid & 3;
#pragma unroll
    for (int mi = 0; mi < 2; mi++) {
        int row0 = bm + rb0 + mi * 16 + g;
#pragma unroll
        for (int ni = 0; ni < NF; ni++) {
            int col = bn + nb0 + ni * 8 + t * 2;
            if (MODE == 0) {
                int c2 = (col & (DI - 1));
                *reinterpret_cast<__nv_bfloat162*>(Cb + (size_t)row0 * DI + c2) =
                    __nv_bfloat162(__float2bfloat16(acc[mi][ni][0]),
                                   __float2bfloat16(acc[mi][ni][1]));
                *reinterpret_cast<__nv_bfloat162*>(Cb + (size_t)(row0 + 8) * DI + c2) =
                    __nv_bfloat162(__float2bfloat16(acc[mi][ni][2]),
                                   __float2bfloat16(acc[mi][ni][3]));
                continue;
            }
            if (MODE == 1 && col >= XPD) continue;
            float2* p0 = reinterpret_cast<float2*>(C + (size_t)row0 * ldC + col);
            float2* p1 = reinterpret_cast<float2*>(C + (size_t)(row0 + 8) * ldC + col);
            float2 v0 = make_float2(acc[mi][ni][0], acc[mi][ni][1]);
            float2 v1 = make_float2(acc[mi][ni][2], acc[mi][ni][3]);
            if (ACC) {
                float2 o0 = *p0, o1 = *p1;
                v0.x += o0.x; v0.y += o0.y; v1.x += o1.x; v1.y += o1.y;
            }
            *p0 = v0; *p1 = v1;
            if (MODE == 2) {
                int lr0 = rb0 + mi * 16 + g;
                ct[lr0 * CTSTR + col] = v0.x; ct[lr0 * CTSTR + col + 1] = v0.y;
                ct[(lr0 + 8) * CTSTR + col] = v1.x; ct[(lr0 + 8) * CTSTR + col + 1] = v1.y;
            }
        }
    }
    if (MODE == 2 && nwp != nullptr) {
        __syncthreads();
        float4 wv = reinterpret_cast<const float4*>(nwp)[lid];
#pragma unroll 4
        for (int rr = 0; rr < 16; rr++) {
            int lr = wid * 16 + rr;
            float4 v = *reinterpret_cast<const float4*>(ct + lr * CTSTR + lid * 4);
            float ss = v.x * v.x + v.y * v.y + v.z * v.z + v.w * v.w;
#pragma unroll
            for (int o = 16; o; o >>= 1) ss += __shfl_xor_sync(0xffffffffu, ss, o);
            float rn = rsqrtf(ss * (1.0f / DM) + EPS);
            __nv_bfloat162 a01 = __nv_bfloat162(__float2bfloat16(v.x * rn * wv.x),
                                                __float2bfloat16(v.y * rn * wv.y));
            __nv_bfloat162 a23 = __nv_bfloat162(__float2bfloat16(v.z * rn * wv.z),
                                                __float2bfloat16(v.w * rn * wv.w));
            size_t base = (size_t)(bm + lr) * DM + lid * 4;
            *reinterpret_cast<__nv_bfloat162*>(g_xn + base)     = a01;
            *reinterpret_cast<__nv_bfloat162*>(g_xn + base + 2) = a23;
        }
    }
    if (MODE == 2 && poolw != nullptr) {
        __syncthreads();
        float* spool = reinterpret_cast<float*>(sm + 128 * CTSTR * 4);  // [8][128]
        float4 wv = reinterpret_cast<const float4*>(poolw)[lid];
        float pa0 = 0.f, pa1 = 0.f, pa2 = 0.f, pa3 = 0.f;
#pragma unroll 4
        for (int rr = 0; rr < 16; rr++) {
            int lr = wid * 16 + rr;
            float4 v = *reinterpret_cast<const float4*>(ct + lr * CTSTR + lid * 4);
            float ss = v.x * v.x + v.y * v.y + v.z * v.z + v.w * v.w;
#pragma unroll
            for (int o = 16; o; o >>= 1) ss += __shfl_xor_sync(0xffffffffu, ss, o);
            float rn = rsqrtf(ss * (1.0f / DM) + EPS);
            pa0 = fmaf(v.x * rn, wv.x, pa0);
            pa1 = fmaf(v.y * rn, wv.y, pa1);
            pa2 = fmaf(v.z * rn, wv.z, pa2);
            pa3 = fmaf(v.w * rn, wv.w, pa3);
        }
        __syncthreads();
        spool[wid * DM + lid * 4 + 0] = pa0;
        spool[wid * DM + lid * 4 + 1] = pa1;
        spool[wid * DM + lid * 4 + 2] = pa2;
        spool[wid * DM + lid * 4 + 3] = pa3;
        __syncthreads();
        if (tid < DM) {
            float s = 0.f;
#pragma unroll
            for (int w = 0; w < 8; w++) s += spool[w * DM + tid];
            g_poolp[blockIdx.x * DM + tid] = s;
        }
    }
}

// ---------------- causal depthwise conv + silu -> bf16 u --------------------
__global__ void k_conv(const float* __restrict__ cw, const float* __restrict__ cb) {
    int d   = threadIdx.x;               // 0..255
    int bl0 = blockIdx.x * 4;            // 4 consecutive rows, same sequence
    int l   = bl0 & (SEQ - 1);
    const __nv_bfloat16* src = g_xm + (size_t)bl0 * DI + d;
    float w0 = cw[d * 4 + 0], w1 = cw[d * 4 + 1], w2 = cw[d * 4 + 2], w3 = cw[d * 4 + 3];
    float b  = cb[d];
    float v0, v1, v2;
    if (l == 0) { v0 = v1 = v2 = 0.f; }
    else {
        v0 = __bfloat162float(src[-3 * DI]);
        v1 = __bfloat162float(src[-2 * DI]);
        v2 = __bfloat162float(src[-DI]);
    }
    float v3 = __bfloat162float(src[0]);
    float v4 = __bfloat162float(src[DI]);
    float v5 = __bfloat162float(src[2 * DI]);
    float v6 = __bfloat162float(src[3 * DI]);
    float va[7] = {v0, v1, v2, v3, v4, v5, v6};
#pragma unroll
    for (int j = 0; j < 4; j++) {
        float s = b;
        s = fmaf(va[j + 0], w0, s);
        s = fmaf(va[j + 1], w1, s);
        s = fmaf(va[j + 2], w2, s);
        s = fmaf(va[j + 3], w3, s);
        float sig = __fdividef(1.0f, 1.0f + __expf(-s));
        g_xc[(size_t)(bl0 + j) * DI + d] = __float2bfloat16(s * sig);
    }
}

// ---------------- fused selective scan (packed f32x2 math) ------------------
// Grid = 256 blocks (one per (b, chunk-pair)), 256 threads (= d).
// __launch_bounds__(256, 2) -> >=2 CTAs/SM -> all blocks co-resident (barrier-safe).
__global__ void __launch_bounds__(256, 2) k_scan(
        const float* __restrict__ Alog, const float* __restrict__ Dpl,
        const float* __restrict__ dtw,  const float* __restrict__ dtb) {
    __shared__ float sdbc[2 * CH * XPD];    // 2 chunks x 64 x 40 floats = 20KB
    const int d  = threadIdx.x;
    const int b  = blockIdx.x >> 4;
    const int cc = blockIdx.x & 15;
    const int c0 = cc * 2;
    const int l0 = b * SEQ + c0 * CH;

    for (int s = d; s < 2 * CH * (XPD / 4); s += DI) {
        reinterpret_cast<float4*>(sdbc)[s] =
            *reinterpret_cast<const float4*>(g_dbc + (size_t)l0 * XPD + s * 4);
    }
    __syncthreads();

    float A[DS];
#pragma unroll
    for (int n = 0; n < DS; n++) A[n] = -__expf(Alog[d * DS + n]);
    const bool fast = a_is_chain(A);
    const float A0 = A[0];
    ull wr2[4];
#pragma unroll
    for (int k = 0; k < 4; k++)
        wr2[k] = pk2(dtw[d * DTR + 2 * k], dtw[d * DTR + 2 * k + 1]);
    const float bb = dtb[d];
    const float Dd = Dpl[d];

    // ---- phase A: local chunk scans -> P, S ----
#pragma unroll
    for (int p = 0; p < 2; p++) {
        const __nv_bfloat16* up = g_xc + (size_t)(l0 + p * CH) * DI + d;
        ull S2[8];
#pragma unroll
        for (int k = 0; k < 8; k++) S2[k] = 0ull;
        float dsum = 0.f;
        for (int t = 0; t < CH; t++) {
            const ulonglong2* rp =
                reinterpret_cast<const ulonglong2*>(sdbc + (p * CH + t) * XPD);
            ulonglong2 dt01 = rp[0], dt23 = rp[1];
            ull v2 = mul2_(dt01.x, wr2[0]);
            v2 = fma2_(dt01.y, wr2[1], v2);
            v2 = fma2_(dt23.x, wr2[2], v2);
            v2 = fma2_(dt23.y, wr2[3], v2);
            float vlo, vhi; upk2(v2, vlo, vhi);
            float delta = softplus_f(vlo + vhi + bb);
            float du = delta * __bfloat162float(up[t * DI]);
            dsum += delta;
            ulonglong2 b01 = rp[2], b23 = rp[3], b45 = rp[4], b67 = rp[5];
            ull B2[8] = {b01.x, b01.y, b23.x, b23.y, b45.x, b45.y, b67.x, b67.y};
            if (fast) {
                ull a2[8];
                powchain2(__expf(delta * A0), a2);
                ull du2 = pk2(du, du);
#pragma unroll
                for (int k = 0; k < 8; k++)
                    S2[k] = fma2_(a2[k], S2[k], mul2_(du2, B2[k]));
            } else {
#pragma unroll
                for (int k = 0; k < 8; k++) {
                    float slo, shi, blo2, bhi2;
                    upk2(S2[k], slo, shi); upk2(B2[k], blo2, bhi2);
                    slo = fmaf(__expf(delta * A[2 * k]), slo, du * blo2);
                    shi = fmaf(__expf(delta * A[2 * k + 1]), shi, du * bhi2);
                    S2[k] = pk2(slo, shi);
                }
            }
        }
        int o = (((b * NCH + c0 + p) * DI) + d) * DS;
        ull P2[8];
        if (fast) {
            powchain2(__expf(dsum * A0), P2);
        } else {
#pragma unroll
            for (int k = 0; k < 8; k++)
                P2[k] = pk2(__expf(A[2 * k] * dsum), __expf(A[2 * k + 1] * dsum));
        }
        ulonglong2* Pp = reinterpret_cast<ulonglong2*>(g_P + o);
        ulonglong2* Sp = reinterpret_cast<ulonglong2*>(g_S + o);
#pragma unroll
        for (int q = 0; q < 4; q++) {
            Pp[q] = make_ulonglong2(P2[2 * q], P2[2 * q + 1]);
            Sp[q] = make_ulonglong2(S2[2 * q], S2[2 * q + 1]);
        }
    }

    // ---- phase B: chunk-boundary recurrence ----
    gbar(SCAN_BLOCKS);
    {
        int item = blockIdx.x * 256 + d;
        int bb2 = item >> 12;
        int dn  = item & 4095;
        float h = 0.f;
        for (int c = 0; c < NCH; c++) {
            int o = (bb2 * NCH + c) * DI * DS + dn;
            g_H0[o] = h;
            h = fmaf(g_P[o], h, g_S[o]);
        }
    }
    gbar(SCAN_BLOCKS);

    // ---- phase C: corrected replay -> y (bf16) ----
#pragma unroll
    for (int p = 0; p < 2; p++) {
        ull h2[8];
        {
            int o = (((b * NCH + c0 + p) * DI) + d) * DS;
            const ulonglong2* Hp = reinterpret_cast<const ulonglong2*>(g_H0 + o);
#pragma unroll
            for (int q = 0; q < 4; q++) {
                ulonglong2 hv = Hp[q];
                h2[2 * q] = hv.x; h2[2 * q + 1] = hv.y;
            }
        }
        const int lp = l0 + p * CH;
        const __nv_bfloat16* up = g_xc + (size_t)lp * DI + d;
        const __nv_bfloat16* zp = g_z  + (size_t)lp * DI + d;
        for (int t = 0; t < CH; t++) {
            const ulonglong2* rp =
                reinterpret_cast<const ulonglong2*>(sdbc + (p * CH + t) * XPD);
            ulonglong2 dt01 = rp[0], dt23 = rp[1];
            ull v2 = mul2_(dt01.x, wr2[0]);
            v2 = fma2_(dt01.y, wr2[1], v2);
            v2 = fma2_(dt23.x, wr2[2], v2);
            v2 = fma2_(dt23.y, wr2[3], v2);
            float vlo, vhi; upk2(v2, vlo, vhi);
            float delta = softplus_f(vlo + vhi + bb);
            float u  = __bfloat162float(up[t * DI]);
            float du = delta * u;
            ulonglong2 b01 = rp[2], b23 = rp[3], b45 = rp[4], b67 = rp[5];
            ulonglong2 c01 = rp[6], c23 = rp[7], c45 = rp[8], c67 = rp[9];
            ull B2[8] = {b01.x, b01.y, b23.x, b23.y, b45.x, b45.y, b67.x, b67.y};
            ull C2[8] = {c01.x, c01.y, c23.x, c23.y, c45.x, c45.y, c67.x, c67.y};
            ull y2;
            if (fast) {
                ull a2[8];
                powchain2(__expf(delta * A0), a2);
                ull du2 = pk2(du, du);
                h2[0] = fma2_(a2[0], h2[0], mul2_(du2, B2[0]));
                y2 = mul2_(h2[0], C2[0]);
#pragma unroll
                for (int k = 1; k < 8; k++) {
                    h2[k] = fma2_(a2[k], h2[k], mul2_(du2, B2[k]));
                    y2 = fma2_(h2[k], C2[k], y2);
                }
            } else {
                float ylo = 0.f, yhi = 0.f;
#pragma unroll
                for (int k = 0; k < 8; k++) {
                    float hlo, hhi, blo2, bhi2, clo2, chi2;
                    upk2(h2[k], hlo, hhi); upk2(B2[k], blo2, bhi2);
                    upk2(C2[k], clo2, chi2);
                    hlo = fmaf(__expf(delta * A[2 * k]), hlo, du * blo2);
                    hhi = fmaf(__expf(delta * A[2 * k + 1]), hhi, du * bhi2);
                    h2[k] = pk2(hlo, hhi);
                    ylo = fmaf(hlo, clo2, ylo);
                    yhi = fmaf(hhi, chi2, yhi);
                }
                y2 = pk2(ylo, yhi);
            }
            float ylo, yhi; upk2(y2, ylo, yhi);
            float y = fmaf(u, Dd, ylo + yhi);
            float z  = __bfloat162float(zp[t * DI]);
            float sz = z * __fdividef(1.0f, 1.0f + __expf(-z));
            g_y[(size_t)(lp + t) * DI + d] = __float2bfloat16(y * sz);
        }
    }
}

// ---------------- pooled reduce + classifier ----------------
__global__ void k_final(const float* __restrict__ cw, const float* __restrict__ cb,
                        float* __restrict__ out) {
    __shared__ float sp[NB * DM];
    int tid = threadIdx.x;
    for (int idx = tid; idx < NB * DM; idx += 256) {
        int b = idx / DM, m = idx % DM;
        float s = 0.f;
#pragma unroll
        for (int k = 0; k < 16; k++) s += g_poolp[(b * 16 + k) * DM + m];
        sp[idx] = s;
    }
    __syncthreads();
    if (tid < NB * NCLS) {
        int b = tid / NCLS, cc = tid % NCLS;
        float s = 0.f;
#pragma unroll 8
        for (int m = 0; m < DM; m++) s = fmaf(sp[b * DM + m], cw[cc * DM + m], s);
        out[tid] = s * (1.0f / SEQ) + cb[cc];
    }
}

// ---------------- launch ----------------
namespace {
constexpr int SMEM_M0 = 2 * (128 * 40 * 2 + 128 * 40 * 2);  // 40960
constexpr int SMEM_M1 = 2 * (128 * 40 * 2 + 64 * 40 * 2);   // 30720
constexpr int SMEM_M2 = 128 * 132 * 4 + 8 * 128 * 4;        // 71680 (epilogue tile)
}

extern "C" void kernel_launch(void* const* d_in, const int* in_sizes, int n_in,
                              void* d_out, int out_size) {
    const float* x      = (const float*)d_in[0];
    const float* enc_w  = (const float*)d_in[1];
    const float* enc_b  = (const float*)d_in[2];
    const float* norm_w = (const float*)d_in[3];
    const float* in_w   = (const float*)d_in[4];
    const float* conv_w = (const float*)d_in[5];
    const float* conv_b = (const float*)d_in[6];
    const float* xp_w   = (const float*)d_in[7];
    const float* dt_w   = (const float*)d_in[8];
    const float* dt_b   = (const float*)d_in[9];
    const float* A_log  = (const float*)d_in[10];
    const float* Dp     = (const float*)d_in[11];
    const float* out_w  = (const float*)d_in[12];
    const float* nfw    = (const float*)d_in[13];
    const float* cls_w  = (const float*)d_in[14];
    const float* cls_b  = (const float*)d_in[15];
    float* out = (float*)d_out;

    cudaFuncSetAttribute(k_mma<0>, cudaFuncAttributeMaxDynamicSharedMemorySize, SMEM_M0);
    cudaFuncSetAttribute(k_mma<1>, cudaFuncAttributeMaxDynamicSharedMemorySize, SMEM_M1);
    cudaFuncSetAttribute(k_mma<2>, cudaFuncAttributeMaxDynamicSharedMemorySize, SMEM_M2);

    k_cvtw<<<NLAY * 512 * 128 / 256, 256>>>(in_w, xp_w, out_w);
    k_encoder<<<BL, DM>>>(x, enc_w, enc_b, norm_w);   // fused layer-0 rmsnorm

    for (int i = 0; i < NLAY; i++) {
        k_mma<0><<<dim3(BL / 128, 4), 256, SMEM_M0>>>(i, nullptr, nullptr);
        k_conv<<<BL / 4, 256>>>(conv_w + i * DI * 4, conv_b + i * DI);
        k_mma<1><<<dim3(BL / 128, 1), 256, SMEM_M1>>>(i, nullptr, nullptr);
        k_scan<<<SCAN_BLOCKS, DI>>>(A_log + i * DI * DS, Dp + i * DI,
                                    dt_w + i * DI * DTR, dt_b + i * DI);
        k_mma<2><<<dim3(BL / 128, 1), 256, SMEM_M2>>>(
            i,
            (i < NLAY - 1) ? (norm_w + (i + 1) * DM) : nullptr,
            (i == NLAY - 1) ? nfw : nullptr);
    }

    k_final<<<1, 256>>>(cls_w, cls_b, out);
}

// round 16
// speedup vs baseline: 1.5391x; 1.0276x over previous
#include <cuda_runtime.h>
#include <cuda_bf16.h>
#include <math.h>
#include <cstdint>

// ---------------- problem constants ----------------
namespace {
constexpr int NB   = 16;      // batch
constexpr int SEQ  = 2048;    // L
constexpr int DM   = 128;     // d_model
constexpr int DI   = 256;     // d_inner
constexpr int DS   = 16;      // d_state
constexpr int DTR  = 8;       // dt_rank
constexpr int NLAY = 4;
constexpr int NCLS = 5;
constexpr int BL   = NB * SEQ;          // 32768 rows
constexpr int XPD  = DTR + 2 * DS;      // 40
constexpr int NCH  = 32;                // chunks per sequence
constexpr int CH   = SEQ / NCH;         // 64 steps per chunk
constexpr int SCAN_BLOCKS = 256;        // 2 chunks per block; <= co-resident capacity
constexpr float EPS = 1e-5f;
}

typedef unsigned long long ull;

// ---------------- scratch (static __device__, no allocs) ----------------
__device__ float g_h    [BL * DM];            // residual stream
__device__ float g_P    [NB * NCH * DI * DS];
__device__ float g_S    [NB * NCH * DI * DS];
__device__ float g_H0   [NB * NCH * DI * DS];
__device__ float g_poolp[256 * DM];           // per-mma2-block pool partials

// bf16 activations
__device__ __nv_bfloat16 g_xn[BL * DM];       // rmsnorm out
__device__ __nv_bfloat16 g_xm[BL * DI];       // in_proj xm half (conv input)
__device__ __nv_bfloat16 g_z [BL * DI];       // in_proj z half (gate)
__device__ __nv_bfloat16 g_y [BL * DI];       // scan out

// bf16 weights, xp padded 40->64 rows with zeros
__device__ __nv_bfloat16 g_wi[NLAY * 512 * 128];
__device__ __nv_bfloat16 g_wx[NLAY * 64 * 256];
__device__ __nv_bfloat16 g_wo[NLAY * 128 * 256];

// global software barrier state (generation-based; monotonic across replays)
__device__ unsigned g_cnt = 0;
__device__ volatile unsigned g_gen = 0;

__device__ __forceinline__ void gbar(unsigned nb) {
    __syncthreads();
    if (threadIdx.x == 0) {
        __threadfence();
        unsigned gen = g_gen;
        if (atomicAdd(&g_cnt, 1u) == nb - 1) {
            atomicExch(&g_cnt, 0u);
            __threadfence();
            g_gen = gen + 1;
        } else {
            while (g_gen == gen) { }
        }
        __threadfence();
    }
    __syncthreads();
}

// ---------------- helpers ----------------
__device__ __forceinline__ uint32_t smem_u32(const void* p) {
    uint32_t a;
    asm("{ .reg .u64 t; cvta.to.shared.u64 t, %1; cvt.u32.u64 %0, t; }"
        : "=r"(a) : "l"(p));
    return a;
}
__device__ __forceinline__ void ldsm4(uint32_t a, uint32_t& r0, uint32_t& r1,
                                      uint32_t& r2, uint32_t& r3) {
    asm volatile("ldmatrix.sync.aligned.m8n8.x4.shared.b16 {%0,%1,%2,%3}, [%4];"
                 : "=r"(r0), "=r"(r1), "=r"(r2), "=r"(r3) : "r"(a));
}
__device__ __forceinline__ void hmma(float* c, const uint32_t* a,
                                     uint32_t b0, uint32_t b1) {
    asm volatile(
        "mma.sync.aligned.m16n8k16.row.col.f32.bf16.bf16.f32 "
        "{%0,%1,%2,%3}, {%4,%5,%6,%7}, {%8,%9}, {%0,%1,%2,%3};"
        : "+f"(c[0]), "+f"(c[1]), "+f"(c[2]), "+f"(c[3])
        : "r"(a[0]), "r"(a[1]), "r"(a[2]), "r"(a[3]), "r"(b0), "r"(b1));
}
__device__ __forceinline__ void cpa16(uint32_t dst, const void* src) {
    asm volatile("cp.async.cg.shared.global [%0], [%1], 16;" :: "r"(dst), "l"(src));
}
__device__ __forceinline__ void cpa_commit() {
    asm volatile("cp.async.commit_group;" ::: "memory");
}
template <int N> __device__ __forceinline__ void cpa_wait() {
    asm volatile("cp.async.wait_group %0;" :: "n"(N) : "memory");
}
// ---- packed f32x2 primitives (lane-exact fp32) ----
__device__ __forceinline__ ull pk2(float lo, float hi) {
    ull r; asm("mov.b64 %0, {%1, %2};" : "=l"(r) : "f"(lo), "f"(hi)); return r;
}
__device__ __forceinline__ void upk2(ull v, float& lo, float& hi) {
    asm("mov.b64 {%0, %1}, %2;" : "=f"(lo), "=f"(hi) : "l"(v));
}
__device__ __forceinline__ ull mul2_(ull a, ull b) {
    ull r; asm("mul.rn.f32x2 %0, %1, %2;" : "=l"(r) : "l"(a), "l"(b)); return r;
}
__device__ __forceinline__ ull fma2_(ull a, ull b, ull c) {
    ull r; asm("fma.rn.f32x2 %0, %1, %2, %3;" : "=l"(r) : "l"(a), "l"(b), "l"(c));
    return r;
}
// packed power ladder: a2[k] = (w^(2k+1), w^(2k+2)), k=0..7
__device__ __forceinline__ void powchain2(float w, ull* a2) {
    float w2 = w * w;
    ull s2 = pk2(w2, w2);
    a2[0] = pk2(w, w2);
#pragma unroll
    for (int k = 1; k < 8; k++) a2[k] = mul2_(a2[k - 1], s2);
}
__device__ __forceinline__ bool a_is_chain(const float* A) {
    bool f = true;
#pragma unroll
    for (int n = 0; n < DS; n++)
        f = f && (fabsf(A[n] - A[0] * (float)(n + 1)) <= 1e-3f * (float)(n + 1));
    return f;
}
__device__ __forceinline__ float softplus_f(float v) {
    return fmaxf(v, 0.0f) + __logf(1.0f + __expf(-fabsf(v)));
}
__device__ __forceinline__ float silu_f(float s) {
    return s * __fdividef(1.0f, 1.0f + __expf(-s));
}

// ---------------- weight conversion (once per launch) ----------------
__global__ void k_cvtw(const float* __restrict__ in_w,
                       const float* __restrict__ xp_w,
                       const float* __restrict__ out_w) {
    int i = blockIdx.x * 256 + threadIdx.x;
    if (i < NLAY * 512 * 128) g_wi[i] = __float2bfloat16(in_w[i]);
    if (i < NLAY * 64 * 256) {
        int l4 = i / (64 * 256);
        int r  = (i / 256) % 64;
        int c  = i % 256;
        float x = (r < XPD) ? xp_w[((size_t)l4 * XPD + r) * 256 + c] : 0.f;
        g_wx[i] = __float2bfloat16(x);
    }
    if (i < NLAY * 128 * 256) g_wo[i] = __float2bfloat16(out_w[i]);
}

// ---------------- encoder: h = x @ enc_w^T + enc_b, fused layer-0 rmsnorm ----
__global__ void k_encoder(const float* __restrict__ x,
                          const float* __restrict__ ew,
                          const float* __restrict__ eb,
                          const float* __restrict__ nw) {
    int row = blockIdx.x;
    int m   = threadIdx.x;          // 128 threads
    __shared__ float xs[12];
    __shared__ float red[4];
    if (m < 12) xs[m] = x[row * 12 + m];
    __syncthreads();
    float acc = eb[m];
#pragma unroll
    for (int c = 0; c < 12; c++) acc = fmaf(xs[c], ew[m * 12 + c], acc);
    g_h[row * DM + m] = acc;
    float ss = acc * acc;
#pragma unroll
    for (int o = 16; o; o >>= 1) ss += __shfl_xor_sync(0xffffffffu, ss, o);
    if ((m & 31) == 0) red[m >> 5] = ss;
    __syncthreads();
    float tot = red[0] + red[1] + red[2] + red[3];
    float r = rsqrtf(tot * (1.0f / DM) + EPS);
    g_xn[(size_t)row * DM + m] = __float2bfloat16(acc * r * nw[m]);
}

// ---------------- plain-bf16 HMMA GEMM, cp.async 2-stage pipelined ----------
// MODE 0: in_proj  (K=128) -> bf16 g_xm / g_z (N=512, grid.y=4; block fully in one half)
// MODE 2: out_proj (K=256) -> g_h (accumulate) + fused next-rmsnorm (nwp)
//         or fused final rmsnorm+pool partials (poolw) on the last layer.
template <int MODE>
__global__ void __launch_bounds__(256, 2) k_mma(int layer,
                                                const float* __restrict__ nwp,
                                                const float* __restrict__ poolw) {
    constexpr int K   = (MODE == 0) ? 128 : 256;
    constexpr int TN  = 128;
    constexpr int NF  = TN / 16;
    constexpr bool ACC = (MODE == 2);
    constexpr int STR = 40;                       // smem row stride (bf16)
    constexpr int NC  = K / 32;                   // k-chunks
    constexpr int ASZ = 128 * STR * 2;            // bytes per A tile
    constexpr int BSZ = TN * STR * 2;             // bytes per B tile
    constexpr int STG = ASZ + BSZ;                // bytes per stage
    constexpr int CTSTR = 132;                    // fp32 epilogue tile stride

    extern __shared__ __align__(16) char sm[];

    const __nv_bfloat16* Ag = (MODE == 0) ? g_xn : g_y;
    const __nv_bfloat16* W  = (MODE == 0) ? (g_wi + (size_t)layer * 512 * 128)
                                          : (g_wo + (size_t)layer * 128 * 256);
    float* C  = g_h;
    const int ldC = DM;

    const int tid = threadIdx.x;
    const int lid = tid & 31;
    const int wid = tid >> 5;
    const int mw  = wid & 3;
    const int nw  = wid >> 2;
    const int bm  = blockIdx.x * 128;
    const int bn  = blockIdx.y * TN;
    const int rb0 = mw * 32;
    const int nb0 = nw * (TN / 2);

    // MODE 0: block writes wholly into xm (bn<256) or z (bn>=256)
    __nv_bfloat16* Cb = nullptr;
    if (MODE == 0) Cb = (bn < DI) ? g_xm : g_z;

    const uint32_t sb0 = smem_u32(sm);

    auto stage_fn = [&](int kc, int st) {
        uint32_t base = sb0 + (uint32_t)st * STG;
#pragma unroll
        for (int s = tid; s < 512; s += 256) {
            int row = s >> 2, c8 = (s & 3) * 8;
            size_t go = (size_t)(bm + row) * K + kc * 32 + c8;
            cpa16(base + (uint32_t)(row * STR + c8) * 2, Ag + go);
        }
#pragma unroll
        for (int s = tid; s < TN * 4; s += 256) {
            int row = s >> 2, c8 = (s & 3) * 8;
            size_t go = (size_t)(bn + row) * K + kc * 32 + c8;
            cpa16(base + ASZ + (uint32_t)(row * STR + c8) * 2, W + go);
        }
        cpa_commit();
    };

    const int arow = (lid & 7) + ((lid >> 3) & 1) * 8;
    const int acol = (lid >> 4) * 8;
    const int brow = (lid & 7) + ((lid >> 3) >= 2 ? 8 : 0);
    const int bcol = ((lid >> 3) & 1) * 8;

    float acc[2][NF][4];
#pragma unroll
    for (int mi = 0; mi < 2; mi++)
#pragma unroll
        for (int ni = 0; ni < NF; ni++)
#pragma unroll
            for (int q = 0; q < 4; q++) acc[mi][ni][q] = 0.f;

    stage_fn(0, 0);
    if (NC > 1) stage_fn(1, 1);

    for (int kc = 0; kc < NC; kc++) {
        if (kc + 1 < NC) cpa_wait<1>(); else cpa_wait<0>();
        __syncthreads();
        uint32_t base = sb0 + (uint32_t)(kc & 1) * STG;
        uint32_t bA = base, bB = base + ASZ;
#pragma unroll
        for (int ks = 0; ks < 32; ks += 16) {
            uint32_t af[2][4];
#pragma unroll
            for (int mi = 0; mi < 2; mi++) {
                uint32_t aoff =
                    (uint32_t)(((rb0 + mi * 16 + arow) * STR + ks + acol) * 2);
                ldsm4(bA + aoff, af[mi][0], af[mi][1], af[mi][2], af[mi][3]);
            }
            uint32_t bf[NF][2];
#pragma unroll
            for (int nj = 0; nj < NF / 2; nj++) {
                uint32_t r0, r1, r2, r3;
                uint32_t boff =
                    (uint32_t)(((nb0 + nj * 16 + brow) * STR + ks + bcol) * 2);
                ldsm4(bB + boff, r0, r1, r2, r3);
                bf[nj * 2][0] = r0; bf[nj * 2][1] = r1;
                bf[nj * 2 + 1][0] = r2; bf[nj * 2 + 1][1] = r3;
            }
#pragma unroll
            for (int mi = 0; mi < 2; mi++)
#pragma unroll
                for (int ni = 0; ni < NF; ni++)
                    hmma(acc[mi][ni], af[mi], bf[ni][0], bf[ni][1]);
        }
        __syncthreads();
        if (kc + 2 < NC) stage_fn(kc + 2, kc & 1);
    }

    // epilogue
    float* ct = reinterpret_cast<float*>(sm);   // fp32 tile for MODE 2 fusion
    const int g = lid >> 2, t = lid & 3;
#pragma unroll
    for (int mi = 0; mi < 2; mi++) {
        int row0 = bm + rb0 + mi * 16 + g;
#pragma unroll
        for (int ni = 0; ni < NF; ni++) {
            int col = bn + nb0 + ni * 8 + t * 2;
            if (MODE == 0) {
                int c2 = (col & (DI - 1));
                *reinterpret_cast<__nv_bfloat162*>(Cb + (size_t)row0 * DI + c2) =
                    __nv_bfloat162(__float2bfloat16(acc[mi][ni][0]),
                                   __float2bfloat16(acc[mi][ni][1]));
                *reinterpret_cast<__nv_bfloat162*>(Cb + (size_t)(row0 + 8) * DI + c2) =
                    __nv_bfloat162(__float2bfloat16(acc[mi][ni][2]),
                                   __float2bfloat16(acc[mi][ni][3]));
                continue;
            }
            float2* p0 = reinterpret_cast<float2*>(C + (size_t)row0 * ldC + col);
            float2* p1 = reinterpret_cast<float2*>(C + (size_t)(row0 + 8) * ldC + col);
            float2 v0 = make_float2(acc[mi][ni][0], acc[mi][ni][1]);
            float2 v1 = make_float2(acc[mi][ni][2], acc[mi][ni][3]);
            if (ACC) {
                float2 o0 = *p0, o1 = *p1;
                v0.x += o0.x; v0.y += o0.y; v1.x += o1.x; v1.y += o1.y;
            }
            *p0 = v0; *p1 = v1;
            int lr0 = rb0 + mi * 16 + g;
            ct[lr0 * CTSTR + col] = v0.x; ct[lr0 * CTSTR + col + 1] = v0.y;
            ct[(lr0 + 8) * CTSTR + col] = v1.x; ct[(lr0 + 8) * CTSTR + col + 1] = v1.y;
        }
    }
    if (MODE == 2 && nwp != nullptr) {
        __syncthreads();
        float4 wv = reinterpret_cast<const float4*>(nwp)[lid];
#pragma unroll 4
        for (int rr = 0; rr < 16; rr++) {
            int lr = wid * 16 + rr;
            float4 v = *reinterpret_cast<const float4*>(ct + lr * CTSTR + lid * 4);
            float ss = v.x * v.x + v.y * v.y + v.z * v.z + v.w * v.w;
#pragma unroll
            for (int o = 16; o; o >>= 1) ss += __shfl_xor_sync(0xffffffffu, ss, o);
            float rn = rsqrtf(ss * (1.0f / DM) + EPS);
            __nv_bfloat162 a01 = __nv_bfloat162(__float2bfloat16(v.x * rn * wv.x),
                                                __float2bfloat16(v.y * rn * wv.y));
            __nv_bfloat162 a23 = __nv_bfloat162(__float2bfloat16(v.z * rn * wv.z),
                                                __float2bfloat16(v.w * rn * wv.w));
            size_t base = (size_t)(bm + lr) * DM + lid * 4;
            *reinterpret_cast<__nv_bfloat162*>(g_xn + base)     = a01;
            *reinterpret_cast<__nv_bfloat162*>(g_xn + base + 2) = a23;
        }
    }
    if (MODE == 2 && poolw != nullptr) {
        __syncthreads();
        float* spool = reinterpret_cast<float*>(sm + 128 * CTSTR * 4);  // [8][128]
        float4 wv = reinterpret_cast<const float4*>(poolw)[lid];
        float pa0 = 0.f, pa1 = 0.f, pa2 = 0.f, pa3 = 0.f;
#pragma unroll 4
        for (int rr = 0; rr < 16; rr++) {
            int lr = wid * 16 + rr;
            float4 v = *reinterpret_cast<const float4*>(ct + lr * CTSTR + lid * 4);
            float ss = v.x * v.x + v.y * v.y + v.z * v.z + v.w * v.w;
#pragma unroll
            for (int o = 16; o; o >>= 1) ss += __shfl_xor_sync(0xffffffffu, ss, o);
            float rn = rsqrtf(ss * (1.0f / DM) + EPS);
            pa0 = fmaf(v.x * rn, wv.x, pa0);
            pa1 = fmaf(v.y * rn, wv.y, pa1);
            pa2 = fmaf(v.z * rn, wv.z, pa2);
            pa3 = fmaf(v.w * rn, wv.w, pa3);
        }
        __syncthreads();
        spool[wid * DM + lid * 4 + 0] = pa0;
        spool[wid * DM + lid * 4 + 1] = pa1;
        spool[wid * DM + lid * 4 + 2] = pa2;
        spool[wid * DM + lid * 4 + 3] = pa3;
        __syncthreads();
        if (tid < DM) {
            float s = 0.f;
#pragma unroll
            for (int w = 0; w < 8; w++) s += spool[w * DM + tid];
            g_poolp[blockIdx.x * DM + tid] = s;
        }
    }
}

// ---------------- fused x_proj GEMM + conv + selective scan -----------------
// Grid = 256 blocks (one per (b, chunk-pair) = 128 rows), 256 threads.
// Prologue: conv(xm)->u (bf16) per k-chunk, HMMA u @ wx^T -> sdbc (smem, fp32).
// Phases A/C recompute u via a running 4-tap window over g_xm (1 load/step).
// __launch_bounds__(256, 2) -> >=2 CTAs/SM -> all blocks co-resident (barrier-safe).
__global__ void __launch_bounds__(256, 2) k_scan(
        int layer,
        const float* __restrict__ Alog, const float* __restrict__ Dpl,
        const float* __restrict__ dtw,  const float* __restrict__ dtb,
        const float* __restrict__ cw,   const float* __restrict__ cb) {
    __shared__ float sdbc[2 * CH * XPD];                 // 20480 B
    __shared__ __align__(16) __nv_bfloat16 sA[128 * 40]; // u tile chunk (10240 B)
    __shared__ __align__(16) __nv_bfloat16 sB[64 * 40];  // wx tile chunk (5120 B)

    const int d   = threadIdx.x;
    const int lid = d & 31;
    const int wid = d >> 5;
    const int b   = blockIdx.x >> 4;
    const int cc  = blockIdx.x & 15;
    const int c0  = cc * 2;
    const int l0  = b * SEQ + c0 * CH;

    // ---- prologue: dbc[128, 40] = u[128, 256] @ wx[40(64), 256]^T into smem ----
    {
        const __nv_bfloat16* W = g_wx + (size_t)layer * 64 * 256;
        const int mw = wid & 3, nw = wid >> 2;
        const int rb0 = mw * 32, nb0 = nw * 32;
        const int arow = (lid & 7) + ((lid >> 3) & 1) * 8;
        const int acol = (lid >> 4) * 8;
        const int brow = (lid & 7) + ((lid >> 3) >= 2 ? 8 : 0);
        const int bcol = ((lid >> 3) & 1) * 8;
        const uint32_t sAb = smem_u32(sA), sBb = smem_u32(sB);

        float acc[2][4][4];
#pragma unroll
        for (int mi = 0; mi < 2; mi++)
#pragma unroll
            for (int ni = 0; ni < 4; ni++)
#pragma unroll
                for (int q = 0; q < 4; q++) acc[mi][ni][q] = 0.f;

        // conv staging thread mapping: col within chunk + 16-row segment
        const int ac  = lid;                 // wrong width; use tid-based below
        const int col = d & 31;              // 0..31
        const int r0  = (d >> 5) * 16;       // 0,16,...,112
        const bool seqstart = ((l0 & (SEQ - 1)) == 0);

        for (int kc = 0; kc < 8; kc++) {
            int d0 = kc * 32;
            // stage B: wx rows 0..63, k cols d0..d0+31
            {
                int s = d;                   // 256 threads, 256 16B-chunks
                int row = s >> 2, c8 = (s & 3) * 8;
                *reinterpret_cast<uint4*>(&sB[row * 40 + c8]) =
                    *reinterpret_cast<const uint4*>(W + (size_t)row * 256 + d0 + c8);
            }
            // stage A: u = silu(conv(xm)) for rows 0..127, channel gd
            {
                int gd = d0 + col;
                float4 wv = *reinterpret_cast<const float4*>(cw + gd * 4);
                float bias = cb[gd];
                int lrow = l0 + r0;
                float v0, v1, v2;
                if (r0 == 0 && seqstart) { v0 = v1 = v2 = 0.f; }
                else {
                    v0 = __bfloat162float(g_xm[(size_t)(lrow - 3) * DI + gd]);
                    v1 = __bfloat162float(g_xm[(size_t)(lrow - 2) * DI + gd]);
                    v2 = __bfloat162float(g_xm[(size_t)(lrow - 1) * DI + gd]);
                }
#pragma unroll 4
                for (int r = 0; r < 16; r++) {
                    float v3 = __bfloat162float(g_xm[(size_t)(lrow + r) * DI + gd]);
                    float s = bias;
                    s = fmaf(v0, wv.x, s); s = fmaf(v1, wv.y, s);
                    s = fmaf(v2, wv.z, s); s = fmaf(v3, wv.w, s);
                    sA[(r0 + r) * 40 + col] = __float2bfloat16(silu_f(s));
                    v0 = v1; v1 = v2; v2 = v3;
                }
            }
            __syncthreads();
#pragma unroll
            for (int ks = 0; ks < 32; ks += 16) {
                uint32_t af[2][4];
#pragma unroll
                for (int mi = 0; mi < 2; mi++) {
                    uint32_t aoff =
                        (uint32_t)(((rb0 + mi * 16 + arow) * 40 + ks + acol) * 2);
                    ldsm4(sAb + aoff, af[mi][0], af[mi][1], af[mi][2], af[mi][3]);
                }
                uint32_t bf[4][2];
#pragma unroll
                for (int nj = 0; nj < 2; nj++) {
                    uint32_t r0_, r1_, r2_, r3_;
                    uint32_t boff =
                        (uint32_t)(((nb0 + nj * 16 + brow) * 40 + ks + bcol) * 2);
                    ldsm4(sBb + boff, r0_, r1_, r2_, r3_);
                    bf[nj * 2][0] = r0_; bf[nj * 2][1] = r1_;
                    bf[nj * 2 + 1][0] = r2_; bf[nj * 2 + 1][1] = r3_;
                }
#pragma unroll
                for (int mi = 0; mi < 2; mi++)
#pragma unroll
                    for (int ni = 0; ni < 4; ni++)
                        hmma(acc[mi][ni], af[mi], bf[ni][0], bf[ni][1]);
            }
            __syncthreads();
        }
        // epilogue -> sdbc (fp32)
        const int g = lid >> 2, t = lid & 3;
#pragma unroll
        for (int mi = 0; mi < 2; mi++) {
            int lr = rb0 + mi * 16 + g;
#pragma unroll
            for (int ni = 0; ni < 4; ni++) {
                int colw = nb0 + ni * 8 + t * 2;
                if (colw < XPD) {
                    *reinterpret_cast<float2*>(&sdbc[lr * XPD + colw]) =
                        make_float2(acc[mi][ni][0], acc[mi][ni][1]);
                    *reinterpret_cast<float2*>(&sdbc[(lr + 8) * XPD + colw]) =
                        make_float2(acc[mi][ni][2], acc[mi][ni][3]);
                }
            }
        }
        __syncthreads();
    }

    // ---- per-thread decode (reused in A and C) ----
    float A[DS];
#pragma unroll
    for (int n = 0; n < DS; n++) A[n] = -__expf(Alog[d * DS + n]);
    const bool fast = a_is_chain(A);
    const float A0 = A[0];
    ull wr2[4];
#pragma unroll
    for (int k = 0; k < 4; k++)
        wr2[k] = pk2(dtw[d * DTR + 2 * k], dtw[d * DTR + 2 * k + 1]);
    const float bb = dtb[d];
    const float Dd = Dpl[d];
    const float4 cwv = *reinterpret_cast<const float4*>(cw + d * 4);
    const float cbv = cb[d];

    // ---- phase A: local chunk scans -> P, S (u via running conv window) ----
#pragma unroll
    for (int p = 0; p < 2; p++) {
        const int lp = l0 + p * CH;
        const __nv_bfloat16* xp = g_xm + (size_t)lp * DI + d;
        float v0, v1, v2;
        if ((lp & (SEQ - 1)) == 0) { v0 = v1 = v2 = 0.f; }
        else {
            v0 = __bfloat162float(xp[-3 * DI]);
            v1 = __bfloat162float(xp[-2 * DI]);
            v2 = __bfloat162float(xp[-DI]);
        }
        ull S2[8];
#pragma unroll
        for (int k = 0; k < 8; k++) S2[k] = 0ull;
        float dsum = 0.f;
        for (int t = 0; t < CH; t++) {
            float v3 = __bfloat162float(xp[t * DI]);
            float su = cbv;
            su = fmaf(v0, cwv.x, su); su = fmaf(v1, cwv.y, su);
            su = fmaf(v2, cwv.z, su); su = fmaf(v3, cwv.w, su);
            float u = silu_f(su);
            v0 = v1; v1 = v2; v2 = v3;

            const ulonglong2* rp =
                reinterpret_cast<const ulonglong2*>(sdbc + (p * CH + t) * XPD);
            ulonglong2 dt01 = rp[0], dt23 = rp[1];
            ull v2p = mul2_(dt01.x, wr2[0]);
            v2p = fma2_(dt01.y, wr2[1], v2p);
            v2p = fma2_(dt23.x, wr2[2], v2p);
            v2p = fma2_(dt23.y, wr2[3], v2p);
            float vlo, vhi; upk2(v2p, vlo, vhi);
            float delta = softplus_f(vlo + vhi + bb);
            float du = delta * u;
            dsum += delta;
            ulonglong2 b01 = rp[2], b23 = rp[3], b45 = rp[4], b67 = rp[5];
            ull B2[8] = {b01.x, b01.y, b23.x, b23.y, b45.x, b45.y, b67.x, b67.y};
            if (fast) {
                ull a2[8];
                powchain2(__expf(delta * A0), a2);
                ull du2 = pk2(du, du);
#pragma unroll
                for (int k = 0; k < 8; k++)
                    S2[k] = fma2_(a2[k], S2[k], mul2_(du2, B2[k]));
            } else {
#pragma unroll
                for (int k = 0; k < 8; k++) {
                    float slo, shi, blo2, bhi2;
                    upk2(S2[k], slo, shi); upk2(B2[k], blo2, bhi2);
                    slo = fmaf(__expf(delta * A[2 * k]), slo, du * blo2);
                    shi = fmaf(__expf(delta * A[2 * k + 1]), shi, du * bhi2);
                    S2[k] = pk2(slo, shi);
                }
            }
        }
        int o = (((b * NCH + c0 + p) * DI) + d) * DS;
        ull P2[8];
        if (fast) {
            powchain2(__expf(dsum * A0), P2);
        } else {
#pragma unroll
            for (int k = 0; k < 8; k++)
                P2[k] = pk2(__expf(A[2 * k] * dsum), __expf(A[2 * k + 1] * dsum));
        }
        ulonglong2* Pp = reinterpret_cast<ulonglong2*>(g_P + o);
        ulonglong2* Sp = reinterpret_cast<ulonglong2*>(g_S + o);
#pragma unroll
        for (int q = 0; q < 4; q++) {
            Pp[q] = make_ulonglong2(P2[2 * q], P2[2 * q + 1]);
            Sp[q] = make_ulonglong2(S2[2 * q], S2[2 * q + 1]);
        }
    }

    // ---- phase B: chunk-boundary recurrence ----
    gbar(SCAN_BLOCKS);
    {
        int item = blockIdx.x * 256 + d;
        int bb2 = item >> 12;
        int dn  = item & 4095;
        float h = 0.f;
        for (int c = 0; c < NCH; c++) {
            int o = (bb2 * NCH + c) * DI * DS + dn;
            g_H0[o] = h;
            h = fmaf(g_P[o], h, g_S[o]);
        }
    }
    gbar(SCAN_BLOCKS);

    // ---- phase C: corrected replay -> y (bf16) ----
#pragma unroll
    for (int p = 0; p < 2; p++) {
        ull h2[8];
        {
            int o = (((b * NCH + c0 + p) * DI) + d) * DS;
            const ulonglong2* Hp = reinterpret_cast<const ulonglong2*>(g_H0 + o);
#pragma unroll
            for (int q = 0; q < 4; q++) {
                ulonglong2 hv = Hp[q];
                h2[2 * q] = hv.x; h2[2 * q + 1] = hv.y;
            }
        }
        const int lp = l0 + p * CH;
        const __nv_bfloat16* xp = g_xm + (size_t)lp * DI + d;
        const __nv_bfloat16* zp = g_z  + (size_t)lp * DI + d;
        float v0, v1, v2;
        if ((lp & (SEQ - 1)) == 0) { v0 = v1 = v2 = 0.f; }
        else {
            v0 = __bfloat162float(xp[-3 * DI]);
            v1 = __bfloat162float(xp[-2 * DI]);
            v2 = __bfloat162float(xp[-DI]);
        }
        for (int t = 0; t < CH; t++) {
            float v3 = __bfloat162float(xp[t * DI]);
            float su = cbv;
            su = fmaf(v0, cwv.x, su); su = fmaf(v1, cwv.y, su);
            su = fmaf(v2, cwv.z, su); su = fmaf(v3, cwv.w, su);
            float u = silu_f(su);
            v0 = v1; v1 = v2; v2 = v3;

            const ulonglong2* rp =
                reinterpret_cast<const ulonglong2*>(sdbc + (p * CH + t) * XPD);
            ulonglong2 dt01 = rp[0], dt23 = rp[1];
            ull v2p = mul2_(dt01.x, wr2[0]);
            v2p = fma2_(dt01.y, wr2[1], v2p);
            v2p = fma2_(dt23.x, wr2[2], v2p);
            v2p = fma2_(dt23.y, wr2[3], v2p);
            float vlo, vhi; upk2(v2p, vlo, vhi);
            float delta = softplus_f(vlo + vhi + bb);
            float du = delta * u;
            ulonglong2 b01 = rp[2], b23 = rp[3], b45 = rp[4], b67 = rp[5];
            ulonglong2 c01 = rp[6], c23 = rp[7], c45 = rp[8], c67 = rp[9];
            ull B2[8] = {b01.x, b01.y, b23.x, b23.y, b45.x, b45.y, b67.x, b67.y};
            ull C2[8] = {c01.x, c01.y, c23.x, c23.y, c45.x, c45.y, c67.x, c67.y};
            ull y2;
            if (fast) {
                ull a2[8];
                powchain2(__expf(delta * A0), a2);
                ull du2 = pk2(du, du);
                h2[0] = fma2_(a2[0], h2[0], mul2_(du2, B2[0]));
                y2 = mul2_(h2[0], C2[0]);
#pragma unroll
                for (int k = 1; k < 8; k++) {
                    h2[k] = fma2_(a2[k], h2[k], mul2_(du2, B2[k]));
                    y2 = fma2_(h2[k], C2[k], y2);
                }
            } else {
                float ylo = 0.f, yhi = 0.f;
#pragma unroll
                for (int k = 0; k < 8; k++) {
                    float hlo, hhi, blo2, bhi2, clo2, chi2;
                    upk2(h2[k], hlo, hhi); upk2(B2[k], blo2, bhi2);
                    upk2(C2[k], clo2, chi2);
                    hlo = fmaf(__expf(delta * A[2 * k]), hlo, du * blo2);
                    hhi = fmaf(__expf(delta * A[2 * k + 1]), hhi, du * bhi2);
                    h2[k] = pk2(hlo, hhi);
                    ylo = fmaf(hlo, clo2, ylo);
                    yhi = fmaf(hhi, chi2, yhi);
                }
                y2 = pk2(ylo, yhi);
            }
            float ylo, yhi; upk2(y2, ylo, yhi);
            float y = fmaf(u, Dd, ylo + yhi);
            float z  = __bfloat162float(zp[t * DI]);
            float sz = z * __fdividef(1.0f, 1.0f + __expf(-z));
            g_y[(size_t)(lp + t) * DI + d] = __float2bfloat16(y * sz);
        }
    }
}

// ---------------- pooled reduce + classifier ----------------
__global__ void k_final(const float* __restrict__ cw, const float* __restrict__ cb,
                        float* __restrict__ out) {
    __shared__ float sp[NB * DM];
    int tid = threadIdx.x;
    for (int idx = tid; idx < NB * DM; idx += 256) {
        int b = idx / DM, m = idx % DM;
        float s = 0.f;
#pragma unroll
        for (int k = 0; k < 16; k++) s += g_poolp[(b * 16 + k) * DM + m];
        sp[idx] = s;
    }
    __syncthreads();
    if (tid < NB * NCLS) {
        int b = tid / NCLS, cc = tid % NCLS;
        float s = 0.f;
#pragma unroll 8
        for (int m = 0; m < DM; m++) s = fmaf(sp[b * DM + m], cw[cc * DM + m], s);
        out[tid] = s * (1.0f / SEQ) + cb[cc];
    }
}

// ---------------- launch ----------------
namespace {
constexpr int SMEM_M0 = 2 * (128 * 40 * 2 + 128 * 40 * 2);  // 40960
constexpr int SMEM_M2 = 128 * 132 * 4 + 8 * 128 * 4;        // 71680 (epilogue tile)
}

extern "C" void kernel_launch(void* const* d_in, const int* in_sizes, int n_in,
                              void* d_out, int out_size) {
    const float* x      = (const float*)d_in[0];
    const float* enc_w  = (const float*)d_in[1];
    const float* enc_b  = (const float*)d_in[2];
    const float* norm_w = (const float*)d_in[3];
    const float* in_w   = (const float*)d_in[4];
    const float* conv_w = (const float*)d_in[5];
    const float* conv_b = (const float*)d_in[6];
    const float* xp_w   = (const float*)d_in[7];
    const float* dt_w   = (const float*)d_in[8];
    const float* dt_b   = (const float*)d_in[9];
    const float* A_log  = (const float*)d_in[10];
    const float* Dp     = (const float*)d_in[11];
    const float* out_w  = (const float*)d_in[12];
    const float* nfw    = (const float*)d_in[13];
    const float* cls_w  = (const float*)d_in[14];
    const float* cls_b  = (const float*)d_in[15];
    float* out = (float*)d_out;

    cudaFuncSetAttribute(k_mma<0>, cudaFuncAttributeMaxDynamicSharedMemorySize, SMEM_M0);
    cudaFuncSetAttribute(k_mma<2>, cudaFuncAttributeMaxDynamicSharedMemorySize, SMEM_M2);

    k_cvtw<<<NLAY * 512 * 128 / 256, 256>>>(in_w, xp_w, out_w);
    k_encoder<<<BL, DM>>>(x, enc_w, enc_b, norm_w);   // fused layer-0 rmsnorm

    for (int i = 0; i < NLAY; i++) {
        k_mma<0><<<dim3(BL / 128, 4), 256, SMEM_M0>>>(i, nullptr, nullptr);
        k_scan<<<SCAN_BLOCKS, DI>>>(i, A_log + i * DI * DS, Dp + i * DI,
                                    dt_w + i * DI * DTR, dt_b + i * DI,
                                    conv_w + i * DI * 4, conv_b + i * DI);
        k_mma<2><<<dim3(BL / 128, 1), 256, SMEM_M2>>>(
            i,
            (i < NLAY - 1) ? (norm_w + (i + 1) * DM) : nullptr,
            (i == NLAY - 1) ? nfw : nullptr);
    }

    k_final<<<1, 256>>>(cls_w, cls_b, out);
}